// round 9
// baseline (speedup 1.0000x reference)
#include <cuda_runtime.h>
#include <cuda_bf16.h>
#include <math.h>
#include <stdint.h>

#define Bdim 64
#define Sdim 512
#define Fdim 512
#define Hdim 1024

// ---------------- scratch (static device globals; no runtime allocation) ----
__device__ float g_xp[(size_t)Bdim * Sdim * Hdim];    // xp layer 0
__device__ float g_xp2[(size_t)Bdim * Sdim * Hdim];   // xp layer 1 (helper output)
__device__ float g_h1[(size_t)Bdim * Sdim * Hdim];    // layer-0 hidden seq [t][b][H]
__device__ __nv_bfloat16 g_hh[4][Bdim * Hdim];        // hidden state hi, ring of 4
__device__ __nv_bfloat16 g_hl[4][Bdim * Hdim];        // hidden state lo, ring of 4
__device__ unsigned g_bar_count = 0;
__device__ volatile unsigned g_bar_gen = 0;
__device__ unsigned g_wdone[4];                       // per-chunk-group producer counts
__device__ unsigned g_rdone;                          // reader-completion count

static __device__ __forceinline__ unsigned smem_u32(const void* p) {
    return (unsigned)__cvta_generic_to_shared(p);
}

// ---------------- grid barrier (init only; all CTAs co-resident) ------------
static __device__ __forceinline__ void grid_sync(int nblocks) {
    __syncthreads();
    if (threadIdx.x == 0) {
        __threadfence();
        unsigned g = g_bar_gen;
        if (atomicAdd(&g_bar_count, 1u) == (unsigned)(nblocks - 1)) {
            g_bar_count = 0;
            __threadfence();
            g_bar_gen = g + 1;
        } else {
            while (g_bar_gen == g) {}
        }
        __threadfence();
    }
    __syncthreads();
}

// acquire-style poll: volatile load loop + fence
static __device__ __forceinline__ void poll_ge(volatile unsigned* p, unsigned tgt) {
    if (*p < tgt) { while (*p < tgt) {} }
    __threadfence();
}

// ---------------- mma.sync helpers ------------------------------------------
static __device__ __forceinline__ void ldsm_x4(uint32_t addr, uint32_t* r) {
    asm volatile("ldmatrix.sync.aligned.m8n8.x4.shared.b16 {%0,%1,%2,%3}, [%4];"
                 : "=r"(r[0]), "=r"(r[1]), "=r"(r[2]), "=r"(r[3]) : "r"(addr));
}
static __device__ __forceinline__ void mma16816(float* c, const uint32_t* a,
                                                const uint32_t* b) {
    asm volatile("mma.sync.aligned.m16n8k16.row.col.f32.bf16.bf16.f32 "
                 "{%0,%1,%2,%3}, {%4,%5,%6,%7}, {%8,%9}, {%0,%1,%2,%3};"
                 : "+f"(c[0]), "+f"(c[1]), "+f"(c[2]), "+f"(c[3])
                 : "r"(a[0]), "r"(a[1]), "r"(a[2]), "r"(a[3]),
                   "r"(b[0]), "r"(b[1]));
}

// ============================================================================
// xproj tile (device function): out[m0..+128][n0..+128] = A@Wt^T + ba + bb
// bf16 hi/lo split, 3 accumulating passes. 256 threads.
// ============================================================================
#define SW128(o) ((o) ^ (((o) >> 3) & 0x70))
#define XP_OFF_BIAS 0
#define XP_OFF_AH   1024
#define XP_OFF_AL   (XP_OFF_AH + 16384)
#define XP_OFF_BH   (XP_OFF_AL + 16384)
#define XP_OFF_BL   (XP_OFF_BH + 16384)
#define XP_SMEM     (XP_OFF_BL + 16384)

static __device__ __forceinline__ uint32_t lm_addr(uint32_t base, int r, int ck) {
    return base + r * 128 + ((ck ^ (r & 7)) << 4);
}

static __device__ void xproj_tile(char* xsm, const float* __restrict__ A,
                                  const float* __restrict__ Wt,
                                  const float* __restrict__ ba,
                                  const float* __restrict__ bb,
                                  float* __restrict__ out,
                                  int m0, int n0, int K)
{
    const uint32_t sb = smem_u32(xsm);
    const int tid = threadIdx.x;
    const int wid = tid >> 5;
    const int lane = tid & 31;
    const int wm = wid & 3;
    const int wn = wid >> 2;

    __syncthreads();   // previous tile's epilogue done with sbias
    float* sbias = (float*)(xsm + XP_OFF_BIAS);
    if (tid < 128) sbias[tid] = ba[n0 + tid] + bb[n0 + tid];

    float acc[2][8][4];
#pragma unroll
    for (int mt = 0; mt < 2; mt++)
#pragma unroll
        for (int nt = 0; nt < 8; nt++)
#pragma unroll
            for (int i = 0; i < 4; i++) acc[mt][nt][i] = 0.0f;

    const int NKT = K / 64;
#pragma unroll 1
    for (int kt = 0; kt < NKT; kt++) {
        __syncthreads();
        const float* Asrc = A + (size_t)m0 * K + kt * 64;
        const float* Bsrc = Wt + (size_t)n0 * K + kt * 64;
#pragma unroll
        for (int r = 0; r < 8; r++) {
            int idx = r * 256 + tid;
            int row = idx >> 4;
            int c4 = idx & 15;
            int sw = SW128(row * 128 + c4 * 8);

            float4 v = *(const float4*)&Asrc[(size_t)row * K + c4 * 4];
            __nv_bfloat162 h01 = __floats2bfloat162_rn(v.x, v.y);
            __nv_bfloat162 h23 = __floats2bfloat162_rn(v.z, v.w);
            __nv_bfloat162 l01 = __floats2bfloat162_rn(v.x - __low2float(h01),
                                                       v.y - __high2float(h01));
            __nv_bfloat162 l23 = __floats2bfloat162_rn(v.z - __low2float(h23),
                                                       v.w - __high2float(h23));
            *(uint2*)(xsm + XP_OFF_AH + sw) =
                make_uint2(*(unsigned*)&h01, *(unsigned*)&h23);
            *(uint2*)(xsm + XP_OFF_AL + sw) =
                make_uint2(*(unsigned*)&l01, *(unsigned*)&l23);

            float4 w = *(const float4*)&Bsrc[(size_t)row * K + c4 * 4];
            __nv_bfloat162 wh01 = __floats2bfloat162_rn(w.x, w.y);
            __nv_bfloat162 wh23 = __floats2bfloat162_rn(w.z, w.w);
            __nv_bfloat162 wl01 = __floats2bfloat162_rn(w.x - __low2float(wh01),
                                                        w.y - __high2float(wh01));
            __nv_bfloat162 wl23 = __floats2bfloat162_rn(w.z - __low2float(wh23),
                                                        w.w - __high2float(wh23));
            *(uint2*)(xsm + XP_OFF_BH + sw) =
                make_uint2(*(unsigned*)&wh01, *(unsigned*)&wh23);
            *(uint2*)(xsm + XP_OFF_BL + sw) =
                make_uint2(*(unsigned*)&wl01, *(unsigned*)&wl23);
        }
        __syncthreads();

        const int asub = lane >> 3;
        const int arow = (asub & 1) * 8 + (lane & 7);
        const int ack = asub >> 1;
        const int brow = ((lane >> 4) & 1) * 8 + (lane & 7);
        const int bck = (lane >> 3) & 1;

#pragma unroll
        for (int p = 0; p < 3; p++) {
            uint32_t aBase = sb + ((p == 2) ? XP_OFF_AL : XP_OFF_AH);
            uint32_t bBase = sb + ((p == 1) ? XP_OFF_BL : XP_OFF_BH);
#pragma unroll
            for (int kk = 0; kk < 4; kk++) {
                uint32_t afrag[2][4], bfrag[8][2];
#pragma unroll
                for (int mt = 0; mt < 2; mt++)
                    ldsm_x4(lm_addr(aBase, wm * 32 + mt * 16 + arow, kk * 2 + ack),
                            afrag[mt]);
#pragma unroll
                for (int np = 0; np < 4; np++) {
                    uint32_t r4[4];
                    ldsm_x4(lm_addr(bBase, wn * 64 + np * 16 + brow, kk * 2 + bck), r4);
                    bfrag[np * 2][0] = r4[0]; bfrag[np * 2][1] = r4[1];
                    bfrag[np * 2 + 1][0] = r4[2]; bfrag[np * 2 + 1][1] = r4[3];
                }
#pragma unroll
                for (int mt = 0; mt < 2; mt++)
#pragma unroll
                    for (int nt = 0; nt < 8; nt++)
                        mma16816(acc[mt][nt], afrag[mt], bfrag[nt]);
            }
        }
    }

#pragma unroll
    for (int mt = 0; mt < 2; mt++) {
#pragma unroll
        for (int nt = 0; nt < 8; nt++) {
            int m = m0 + wm * 32 + mt * 16 + (lane >> 2);
            int nl = wn * 64 + nt * 8 + (lane & 3) * 2;
            float2 o0, o1;
            o0.x = acc[mt][nt][0] + sbias[nl];
            o0.y = acc[mt][nt][1] + sbias[nl + 1];
            o1.x = acc[mt][nt][2] + sbias[nl];
            o1.y = acc[mt][nt][3] + sbias[nl + 1];
            *(float2*)&out[(size_t)m * Hdim + n0 + nl] = o0;
            *(float2*)&out[(size_t)(m + 8) * Hdim + n0 + nl] = o1;
        }
    }
}

// standalone xproj kernel (layer-0 xp)
template <int K>
__global__ void __launch_bounds__(256, 2) xproj_mma_kernel(
    const float* __restrict__ A, const float* __restrict__ Wt,
    const float* __restrict__ ba, const float* __restrict__ bb,
    float* __restrict__ out)
{
    extern __shared__ __align__(1024) char xsm[];
    xproj_tile(xsm, A, Wt, ba, bb, out, blockIdx.y * 128, blockIdx.x * 128, K);
}

// ============================================================================
// Recurrence (flag-dataflow) + fused layer-1 xproj helpers.
// CTAs [0, nrnn): rnn, 16 output neurons each, 4-deep h ring, chunk flags.
// CTAs [nrnn, nrnn+nhelp): xproj helpers for layer-1 xp (consume h1 as ready).
// ============================================================================
#define RNN_OFF_W    0
#define RNN_OFF_S0   65536
#define RNN_OFF_S1   131072
#define RNN_SMEM_BYTES 196608

static __device__ __forceinline__ void stage_h2(
    const __nv_bfloat16* __restrict__ hh, const __nv_bfloat16* __restrict__ hl,
    int kc, char* dst, int tid)
{
#pragma unroll
    for (int r = 0; r < 8; r++) {
        int idx = r * 256 + tid;
        int b = idx >> 5;
        int lg = idx & 31;
        uint32_t d = smem_u32(dst + b * 512 + ((lg ^ (b & 7)) << 4));
        const __nv_bfloat16* s = hh + b * Hdim + kc * 256 + lg * 8;
        asm volatile("cp.async.cg.shared.global [%0], [%1], 16;" ::"r"(d), "l"(s));
        const __nv_bfloat16* s2 = hl + b * Hdim + kc * 256 + lg * 8;
        asm volatile("cp.async.cg.shared.global [%0], [%1], 16;"
                     ::"r"(d + 32768), "l"(s2));
    }
}

__global__ void __launch_bounds__(256) rnn_kernel(
    const float* __restrict__ xp, const float* __restrict__ Whh,
    float* __restrict__ out_seq, long long strideB, long long strideT,
    const float* __restrict__ hA, const float* __restrict__ Wih,
    const float* __restrict__ bi, const float* __restrict__ bh2,
    float* __restrict__ xpo, int nrnn, int nhelp)
{
    extern __shared__ __align__(1024) char smraw[];
    const int tid = threadIdx.x;
    const int bid = blockIdx.x;

    if (bid == 0 && tid < 4) g_wdone[tid] = 0;
    if (bid == 0 && tid == 4) g_rdone = 0;

    if (bid >= nrnn) {
        // -------- helper: layer-1 xproj tiles, consumed as h1 becomes ready --
        grid_sync(nrnn + nhelp);
        int hidx = bid - nrnn;
        for (int idx = hidx; idx < 2048; idx += nhelp) {
            int mt = idx >> 3, nt = idx & 7;
            unsigned tgt = 32u * (unsigned)(mt + 1);    // steps 2mt,2mt+1 done
            poll_ge(&g_wdone[0], tgt);
            poll_ge(&g_wdone[1], tgt);
            poll_ge(&g_wdone[2], tgt);
            poll_ge(&g_wdone[3], tgt);
            xproj_tile(smraw, hA, Wih, bi, bh2, xpo, mt * 128, nt * 128, Hdim);
        }
        return;
    }

    // -------- rnn role ------------------------------------------------------
    const int wid = tid >> 5;
    const int lane = tid & 31;
    const int j0 = bid * 16;
    const int cgrp = bid >> 4;

    const uint32_t whbase = smem_u32(smraw + RNN_OFF_W);
    const uint32_t wlbase = whbase + 32768;
    float* p_s = (float*)(smraw + RNN_OFF_S0);

    // load W slice (16 x 1024 fp32) -> bf16 hi/lo swizzled SMEM
    for (int i = tid; i < 4096; i += 256) {
        int j = i >> 8;
        int col4 = i & 255;
        float4 v = *(const float4*)&Whh[(size_t)(j0 + j) * Hdim + col4 * 4];
        __nv_bfloat162 h01 = __floats2bfloat162_rn(v.x, v.y);
        __nv_bfloat162 h23 = __floats2bfloat162_rn(v.z, v.w);
        __nv_bfloat162 l01 = __floats2bfloat162_rn(v.x - __low2float(h01),
                                                   v.y - __high2float(h01));
        __nv_bfloat162 l23 = __floats2bfloat162_rn(v.z - __low2float(h23),
                                                   v.w - __high2float(h23));
        int g = col4 >> 1;
        int off = j * 2048 + ((g ^ (j & 7)) << 4) + (col4 & 1) * 8;
        *(uint2*)(smraw + RNN_OFF_W + off) =
            make_uint2(*(unsigned*)&h01, *(unsigned*)&h23);
        *(uint2*)(smraw + RNN_OFF_W + 32768 + off) =
            make_uint2(*(unsigned*)&l01, *(unsigned*)&l23);
    }
    // zero initial hidden state slice (ALL 16 owned columns, ring buf 0)
    if (tid < 64) {
        uint4 z = make_uint4(0, 0, 0, 0);
        *(uint4*)&g_hh[0][(size_t)tid * Hdim + j0] = z;
        *(uint4*)&g_hh[0][(size_t)tid * Hdim + j0 + 8] = z;
        *(uint4*)&g_hl[0][(size_t)tid * Hdim + j0] = z;
        *(uint4*)&g_hl[0][(size_t)tid * Hdim + j0 + 8] = z;
    }
    grid_sync(nrnn + nhelp);

    const int asub = lane >> 3;
    const int arow = (asub & 1) * 8 + (lane & 7);
    const int ack = asub >> 1;
    const int brow = ((lane >> 4) & 1) * 8 + (lane & 7);
    const int bck = (lane >> 3) & 1;
    const int eb = tid >> 2;
    const int ej = (tid & 3) * 4;

#pragma unroll 1
    for (int t = 0; t < Sdim; t++) {
        const __nv_bfloat16* hh_in = g_hh[t & 3];
        const __nv_bfloat16* hl_in = g_hl[t & 3];
        __nv_bfloat16* hh_out = g_hh[(t + 1) & 3];
        __nv_bfloat16* hl_out = g_hl[(t + 1) & 3];

        float4 xpv = *(const float4*)&xp[(size_t)eb * strideB + (size_t)t * strideT
                                         + j0 + ej];

        float acc[4][2][4];
#pragma unroll
        for (int mt = 0; mt < 4; mt++)
#pragma unroll
            for (int nt = 0; nt < 2; nt++)
#pragma unroll
                for (int i = 0; i < 4; i++) acc[mt][nt][i] = 0.0f;

        // WAR: readers of ring buf (t+1)&3 (= step t-3 readers) must be done
        if (t >= 3) poll_ge(&g_rdone, 64u * (unsigned)(t - 2));

        const unsigned wtgt = 16u * (unsigned)t;
        {
            int cc = cgrp & 3;
            if (t) poll_ge(&g_wdone[cc], wtgt);
            stage_h2(hh_in, hl_in, cc, smraw + RNN_OFF_S0, tid);
            asm volatile("cp.async.commit_group;");
            cc = (cgrp + 1) & 3;
            if (t) poll_ge(&g_wdone[cc], wtgt);
            stage_h2(hh_in, hl_in, cc, smraw + RNN_OFF_S1, tid);
            asm volatile("cp.async.commit_group;");
        }

#pragma unroll
        for (int c = 0; c < 4; c++) {
            int cc = (cgrp + c) & 3;
            if (c < 3) asm volatile("cp.async.wait_group 1;");
            else       asm volatile("cp.async.wait_group 0;");
            __syncthreads();
            if (c == 3 && tid == 0) atomicAdd(&g_rdone, 1u);  // all step reads done

            const uint32_t shbase = smem_u32(smraw +
                ((c & 1) ? RNN_OFF_S1 : RNN_OFF_S0));
            const uint32_t slbase = shbase + 32768;

#pragma unroll
            for (int s2 = 0; s2 < 2; s2++) {
                uint32_t ah[4][4], al[4][4];
                int gA = wid * 4 + s2 * 2 + ack;
#pragma unroll
                for (int mt = 0; mt < 4; mt++) {
                    int row = mt * 16 + arow;
                    uint32_t sw = (uint32_t)((gA ^ (row & 7)) << 4);
                    ldsm_x4(shbase + row * 512 + sw, ah[mt]);
                    ldsm_x4(slbase + row * 512 + sw, al[mt]);
                }
                int sg = cc * 16 + wid * 2 + s2;
                int gB = sg * 2 + bck;
                uint32_t bh[4], bl[4];
                uint32_t bsw = (uint32_t)((gB ^ (brow & 7)) << 4);
                ldsm_x4(whbase + brow * 2048 + bsw, bh);
                ldsm_x4(wlbase + brow * 2048 + bsw, bl);

#pragma unroll
                for (int mt = 0; mt < 4; mt++) {
                    mma16816(acc[mt][0], ah[mt], &bh[0]);
                    mma16816(acc[mt][1], ah[mt], &bh[2]);
                    mma16816(acc[mt][0], ah[mt], &bl[0]);
                    mma16816(acc[mt][1], ah[mt], &bl[2]);
                    mma16816(acc[mt][0], al[mt], &bh[0]);
                    mma16816(acc[mt][1], al[mt], &bh[2]);
                }
            }
            __syncthreads();
            if (c + 2 < 4) {
                int cn = (cgrp + c + 2) & 3;
                if (t) poll_ge(&g_wdone[cn], wtgt);
                stage_h2(hh_in, hl_in, cn,
                         smraw + ((c & 1) ? RNN_OFF_S1 : RNN_OFF_S0), tid);
                asm volatile("cp.async.commit_group;");
            }
        }

        // cross-warp reduce via SMEM partials (alias stage buf 0)
#pragma unroll
        for (int mt = 0; mt < 4; mt++)
#pragma unroll
            for (int nt = 0; nt < 2; nt++) {
                int b = mt * 16 + (lane >> 2);
                int j = nt * 8 + (lane & 3) * 2;
                *(float2*)&p_s[wid * 1024 + b * 16 + j] =
                    make_float2(acc[mt][nt][0], acc[mt][nt][1]);
                *(float2*)&p_s[wid * 1024 + (b + 8) * 16 + j] =
                    make_float2(acc[mt][nt][2], acc[mt][nt][3]);
            }
        __syncthreads();

        {
            int o = tid * 4;
            float4 s = *(const float4*)&p_s[o];
#pragma unroll
            for (int w = 1; w < 8; w++) {
                float4 q = *(const float4*)&p_s[w * 1024 + o];
                s.x += q.x; s.y += q.y; s.z += q.z; s.w += q.w;
            }
            float v0 = tanhf(s.x + xpv.x);
            float v1 = tanhf(s.y + xpv.y);
            float v2 = tanhf(s.z + xpv.z);
            float v3 = tanhf(s.w + xpv.w);

            __nv_bfloat162 h01 = __floats2bfloat162_rn(v0, v1);
            __nv_bfloat162 h23 = __floats2bfloat162_rn(v2, v3);
            __nv_bfloat162 l01 = __floats2bfloat162_rn(v0 - __low2float(h01),
                                                       v1 - __high2float(h01));
            __nv_bfloat162 l23 = __floats2bfloat162_rn(v2 - __low2float(h23),
                                                       v3 - __high2float(h23));
            size_t ho = (size_t)eb * Hdim + j0 + ej;
            *(uint2*)&hh_out[ho] = make_uint2(*(unsigned*)&h01, *(unsigned*)&h23);
            *(uint2*)&hl_out[ho] = make_uint2(*(unsigned*)&l01, *(unsigned*)&l23);
            if (out_seq)
                *(float4*)&out_seq[((size_t)t * Bdim + eb) * Hdim + j0 + ej] =
                    make_float4(v0, v1, v2, v3);
        }
        __syncthreads();
        if (tid == 0) {
            __threadfence();
            atomicAdd(&g_wdone[cgrp], 1u);   // publish step t output
        }
    }
}

// ============================================================================
// Final FC + sigmoid: h_last = g_hh[0] + g_hl[0] (ring slot 0 after 512 steps)
// ============================================================================
__global__ void fc_kernel(const __nv_bfloat16* __restrict__ hh,
                          const __nv_bfloat16* __restrict__ hl,
                          const float* __restrict__ fcw,
                          const float* __restrict__ fcb,
                          float* __restrict__ out)
{
    __shared__ float red[8];
    int b = blockIdx.x, tid = threadIdx.x;
    float s = 0.0f;
    for (int k = tid; k < Hdim; k += 256) {
        float h = __bfloat162float(hh[b * Hdim + k]) +
                  __bfloat162float(hl[b * Hdim + k]);
        s += h * fcw[k];
    }
#pragma unroll
    for (int o = 16; o; o >>= 1) s += __shfl_xor_sync(0xFFFFFFFFu, s, o);
    if ((tid & 31) == 0) red[tid >> 5] = s;
    __syncthreads();
    if (tid == 0) {
        float tot = 0.0f;
#pragma unroll
        for (int i = 0; i < 8; i++) tot += red[i];
        float logit = tot + fcb[0];
        out[b] = 1.0f / (1.0f + expf(-logit));
    }
}

// ============================================================================
extern "C" void kernel_launch(void* const* d_in, const int* in_sizes, int n_in,
                              void* d_out, int out_size)
{
    const float* x     = (const float*)d_in[0];
    const float* W_ih0 = (const float*)d_in[1];
    const float* W_hh0 = (const float*)d_in[2];
    const float* b_ih0 = (const float*)d_in[3];
    const float* b_hh0 = (const float*)d_in[4];
    const float* W_ih1 = (const float*)d_in[5];
    const float* W_hh1 = (const float*)d_in[6];
    const float* b_ih1 = (const float*)d_in[7];
    const float* b_hh1 = (const float*)d_in[8];
    const float* fc_w  = (const float*)d_in[9];
    const float* fc_b  = (const float*)d_in[10];
    float* out = (float*)d_out;

    float *xp, *xp2, *h1;
    __nv_bfloat16 *hh, *hl;
    cudaGetSymbolAddress((void**)&xp, g_xp);
    cudaGetSymbolAddress((void**)&xp2, g_xp2);
    cudaGetSymbolAddress((void**)&h1, g_h1);
    cudaGetSymbolAddress((void**)&hh, g_hh);
    cudaGetSymbolAddress((void**)&hl, g_hl);

    cudaFuncSetAttribute(rnn_kernel, cudaFuncAttributeMaxDynamicSharedMemorySize,
                         RNN_SMEM_BYTES);
    cudaFuncSetAttribute(xproj_mma_kernel<Fdim>,
                         cudaFuncAttributeMaxDynamicSharedMemorySize, XP_SMEM);

    dim3 xgrid(8, 256);

    // layer-0 xp: rows m = b*S + t -> xp[(b*S+t)*H + j]
    xproj_mma_kernel<Fdim><<<xgrid, 256, XP_SMEM>>>(x, W_ih0, b_ih0, b_hh0, xp);
    // layer-0 rnn (64 CTAs) + layer-1 xproj helpers (84 CTAs) fused
    rnn_kernel<<<148, 256, RNN_SMEM_BYTES>>>(
        xp, W_hh0, h1, (long long)Sdim * Hdim, (long long)Hdim,
        h1, W_ih1, b_ih1, b_hh1, xp2, 64, 84);
    // layer-1 rnn (64 CTAs, no helpers); xp1 rows m = t*B + b
    rnn_kernel<<<64, 256, RNN_SMEM_BYTES>>>(
        xp2, W_hh1, nullptr, (long long)Hdim, (long long)Bdim * Hdim,
        nullptr, nullptr, nullptr, nullptr, nullptr, 64, 0);
    // head: final h2 state is in ring slot 512 & 3 = 0
    fc_kernel<<<64, 256>>>(hh, hl, fc_w, fc_b, out);
}

// round 10
// speedup vs baseline: 1.4335x; 1.4335x over previous
#include <cuda_runtime.h>
#include <cuda_bf16.h>
#include <math.h>
#include <stdint.h>

#define Bdim 64
#define Sdim 512
#define Fdim 512
#define Hdim 1024

// ---------------- scratch (static device globals; no runtime allocation) ----
__device__ float g_xp[(size_t)Bdim * Sdim * Hdim];    // xp layer 0
__device__ float g_xp2[(size_t)Bdim * Sdim * Hdim];   // xp layer 1 (helper output)
__device__ float g_h1[(size_t)Bdim * Sdim * Hdim];    // layer-0 hidden seq [t][b][H]
__device__ __nv_bfloat16 g_hh[2][Bdim * Hdim];        // hidden hi, [b][k], dbl-buf
__device__ __nv_bfloat16 g_hl[2][Bdim * Hdim];        // hidden lo
__device__ unsigned g_bar_count = 0;
__device__ unsigned g_bar_gen = 0;
__device__ unsigned g_step = 0;                       // completed CTA-steps (64/step)

static __device__ __forceinline__ unsigned smem_u32(const void* p) {
    return (unsigned)__cvta_generic_to_shared(p);
}

// ---------------- grid barrier: scoped release/acquire, no membar.gl --------
static __device__ __forceinline__ void grid_sync(int nblocks) {
    __syncthreads();
    if (threadIdx.x == 0) {
        unsigned g;
        asm volatile("ld.relaxed.gpu.global.u32 %0, [%1];"
                     : "=r"(g) : "l"(&g_bar_gen));
        unsigned old;
        asm volatile("atom.acq_rel.gpu.global.add.u32 %0, [%1], 1;"
                     : "=r"(old) : "l"(&g_bar_count) : "memory");
        if (old == (unsigned)(nblocks - 1)) {
            asm volatile("st.relaxed.gpu.global.u32 [%0], %1;"
                         :: "l"(&g_bar_count), "r"(0u) : "memory");
            asm volatile("st.release.gpu.global.u32 [%0], %1;"
                         :: "l"(&g_bar_gen), "r"(g + 1) : "memory");
        } else {
            unsigned cur;
            do {
                asm volatile("ld.acquire.gpu.global.u32 %0, [%1];"
                             : "=r"(cur) : "l"(&g_bar_gen) : "memory");
            } while (cur == g);
        }
    }
    __syncthreads();
}

// ---------------- mma.sync helpers ------------------------------------------
static __device__ __forceinline__ void ldsm_x4(uint32_t addr, uint32_t* r) {
    asm volatile("ldmatrix.sync.aligned.m8n8.x4.shared.b16 {%0,%1,%2,%3}, [%4];"
                 : "=r"(r[0]), "=r"(r[1]), "=r"(r[2]), "=r"(r[3]) : "r"(addr));
}
static __device__ __forceinline__ void mma16816(float* c, const uint32_t* a,
                                                const uint32_t* b) {
    asm volatile("mma.sync.aligned.m16n8k16.row.col.f32.bf16.bf16.f32 "
                 "{%0,%1,%2,%3}, {%4,%5,%6,%7}, {%8,%9}, {%0,%1,%2,%3};"
                 : "+f"(c[0]), "+f"(c[1]), "+f"(c[2]), "+f"(c[3])
                 : "r"(a[0]), "r"(a[1]), "r"(a[2]), "r"(a[3]),
                   "r"(b[0]), "r"(b[1]));
}

// ============================================================================
// xproj tile: out[m0..+128][n0..+128] = A@Wt^T + ba + bb (bf16 hi/lo, 3-pass)
// ============================================================================
#define SW128(o) ((o) ^ (((o) >> 3) & 0x70))
#define XP_OFF_BIAS 0
#define XP_OFF_AH   1024
#define XP_OFF_AL   (XP_OFF_AH + 16384)
#define XP_OFF_BH   (XP_OFF_AL + 16384)
#define XP_OFF_BL   (XP_OFF_BH + 16384)
#define XP_SMEM     (XP_OFF_BL + 16384)

static __device__ __forceinline__ uint32_t lm_addr(uint32_t base, int r, int ck) {
    return base + r * 128 + ((ck ^ (r & 7)) << 4);
}

static __device__ void xproj_tile(char* xsm, const float* __restrict__ A,
                                  const float* __restrict__ Wt,
                                  const float* __restrict__ ba,
                                  const float* __restrict__ bb,
                                  float* __restrict__ out,
                                  int m0, int n0, int K)
{
    const uint32_t sb = smem_u32(xsm);
    const int tid = threadIdx.x;
    const int wid = tid >> 5;
    const int lane = tid & 31;
    const int wm = wid & 3;
    const int wn = wid >> 2;

    __syncthreads();
    float* sbias = (float*)(xsm + XP_OFF_BIAS);
    if (tid < 128) sbias[tid] = ba[n0 + tid] + bb[n0 + tid];

    float acc[2][8][4];
#pragma unroll
    for (int mt = 0; mt < 2; mt++)
#pragma unroll
        for (int nt = 0; nt < 8; nt++)
#pragma unroll
            for (int i = 0; i < 4; i++) acc[mt][nt][i] = 0.0f;

    const int NKT = K / 64;
#pragma unroll 1
    for (int kt = 0; kt < NKT; kt++) {
        __syncthreads();
        const float* Asrc = A + (size_t)m0 * K + kt * 64;
        const float* Bsrc = Wt + (size_t)n0 * K + kt * 64;
#pragma unroll
        for (int r = 0; r < 8; r++) {
            int idx = r * 256 + tid;
            int row = idx >> 4;
            int c4 = idx & 15;
            int sw = SW128(row * 128 + c4 * 8);

            float4 v = *(const float4*)&Asrc[(size_t)row * K + c4 * 4];
            __nv_bfloat162 h01 = __floats2bfloat162_rn(v.x, v.y);
            __nv_bfloat162 h23 = __floats2bfloat162_rn(v.z, v.w);
            __nv_bfloat162 l01 = __floats2bfloat162_rn(v.x - __low2float(h01),
                                                       v.y - __high2float(h01));
            __nv_bfloat162 l23 = __floats2bfloat162_rn(v.z - __low2float(h23),
                                                       v.w - __high2float(h23));
            *(uint2*)(xsm + XP_OFF_AH + sw) =
                make_uint2(*(unsigned*)&h01, *(unsigned*)&h23);
            *(uint2*)(xsm + XP_OFF_AL + sw) =
                make_uint2(*(unsigned*)&l01, *(unsigned*)&l23);

            float4 w = *(const float4*)&Bsrc[(size_t)row * K + c4 * 4];
            __nv_bfloat162 wh01 = __floats2bfloat162_rn(w.x, w.y);
            __nv_bfloat162 wh23 = __floats2bfloat162_rn(w.z, w.w);
            __nv_bfloat162 wl01 = __floats2bfloat162_rn(w.x - __low2float(wh01),
                                                        w.y - __high2float(wh01));
            __nv_bfloat162 wl23 = __floats2bfloat162_rn(w.z - __low2float(wh23),
                                                        w.w - __high2float(wh23));
            *(uint2*)(xsm + XP_OFF_BH + sw) =
                make_uint2(*(unsigned*)&wh01, *(unsigned*)&wh23);
            *(uint2*)(xsm + XP_OFF_BL + sw) =
                make_uint2(*(unsigned*)&wl01, *(unsigned*)&wl23);
        }
        __syncthreads();

        const int asub = lane >> 3;
        const int arow = (asub & 1) * 8 + (lane & 7);
        const int ack = asub >> 1;
        const int brow = ((lane >> 4) & 1) * 8 + (lane & 7);
        const int bck = (lane >> 3) & 1;

#pragma unroll
        for (int p = 0; p < 3; p++) {
            uint32_t aBase = sb + ((p == 2) ? XP_OFF_AL : XP_OFF_AH);
            uint32_t bBase = sb + ((p == 1) ? XP_OFF_BL : XP_OFF_BH);
#pragma unroll
            for (int kk = 0; kk < 4; kk++) {
                uint32_t afrag[2][4], bfrag[8][2];
#pragma unroll
                for (int mt = 0; mt < 2; mt++)
                    ldsm_x4(lm_addr(aBase, wm * 32 + mt * 16 + arow, kk * 2 + ack),
                            afrag[mt]);
#pragma unroll
                for (int np = 0; np < 4; np++) {
                    uint32_t r4[4];
                    ldsm_x4(lm_addr(bBase, wn * 64 + np * 16 + brow, kk * 2 + bck), r4);
                    bfrag[np * 2][0] = r4[0]; bfrag[np * 2][1] = r4[1];
                    bfrag[np * 2 + 1][0] = r4[2]; bfrag[np * 2 + 1][1] = r4[3];
                }
#pragma unroll
                for (int mt = 0; mt < 2; mt++)
#pragma unroll
                    for (int nt = 0; nt < 8; nt++)
                        mma16816(acc[mt][nt], afrag[mt], bfrag[nt]);
            }
        }
    }

#pragma unroll
    for (int mt = 0; mt < 2; mt++) {
#pragma unroll
        for (int nt = 0; nt < 8; nt++) {
            int m = m0 + wm * 32 + mt * 16 + (lane >> 2);
            int nl = wn * 64 + nt * 8 + (lane & 3) * 2;
            float2 o0, o1;
            o0.x = acc[mt][nt][0] + sbias[nl];
            o0.y = acc[mt][nt][1] + sbias[nl + 1];
            o1.x = acc[mt][nt][2] + sbias[nl];
            o1.y = acc[mt][nt][3] + sbias[nl + 1];
            *(float2*)&out[(size_t)m * Hdim + n0 + nl] = o0;
            *(float2*)&out[(size_t)(m + 8) * Hdim + n0 + nl] = o1;
        }
    }
}

// standalone xproj kernel (layer-0 xp)
template <int K>
__global__ void __launch_bounds__(256, 2) xproj_mma_kernel(
    const float* __restrict__ A, const float* __restrict__ Wt,
    const float* __restrict__ ba, const float* __restrict__ bb,
    float* __restrict__ out)
{
    extern __shared__ __align__(1024) char xsm[];
    xproj_tile(xsm, A, Wt, ba, bb, out, blockIdx.y * 128, blockIdx.x * 128, K);
}

// ============================================================================
// Recurrence (R8 structure, barrier-per-step) + optional xp1 helper CTAs.
// rnn CTAs [0,nrnn): 16 output neurons each, grid_sync(nrnn) per step,
//   publish one release-increment of g_step per step (layer 0 only).
// helper CTAs [nrnn, nrnn+nhelp): compute xp1 tiles once the two needed
//   timesteps of h1 are published (single-counter acquire poll, off rnn path).
// ============================================================================
#define RNN_OFF_W    0
#define RNN_OFF_S0   65536
#define RNN_OFF_S1   131072
#define RNN_SMEM_BYTES 196608

static __device__ __forceinline__ void stage_h2(
    const __nv_bfloat16* __restrict__ hh, const __nv_bfloat16* __restrict__ hl,
    int kc, char* dst, int tid)
{
#pragma unroll
    for (int r = 0; r < 8; r++) {
        int idx = r * 256 + tid;
        int b = idx >> 5;
        int lg = idx & 31;
        uint32_t d = smem_u32(dst + b * 512 + ((lg ^ (b & 7)) << 4));
        const __nv_bfloat16* s = hh + b * Hdim + kc * 256 + lg * 8;
        asm volatile("cp.async.cg.shared.global [%0], [%1], 16;" ::"r"(d), "l"(s));
        const __nv_bfloat16* s2 = hl + b * Hdim + kc * 256 + lg * 8;
        asm volatile("cp.async.cg.shared.global [%0], [%1], 16;"
                     ::"r"(d + 32768), "l"(s2));
    }
}

__global__ void __launch_bounds__(256) rnn_kernel(
    const float* __restrict__ xp, const float* __restrict__ Whh,
    float* __restrict__ out_seq, long long strideB, long long strideT,
    const float* __restrict__ hA, const float* __restrict__ Wih,
    const float* __restrict__ bi, const float* __restrict__ bh2,
    float* __restrict__ xpo, int nrnn, int nhelp)
{
    extern __shared__ __align__(1024) char smraw[];
    const int tid = threadIdx.x;
    const int bid = blockIdx.x;

    if (bid == 0 && tid == 0)
        asm volatile("st.relaxed.gpu.global.u32 [%0], %1;"
                     :: "l"(&g_step), "r"(0u) : "memory");

    if (bid >= nrnn) {
        // -------- helper: xp1 tiles, gated on h1 step availability ----------
        grid_sync(nrnn + nhelp);
        int hidx = bid - nrnn;
        for (int idx = hidx; idx < 2048; idx += nhelp) {
            int mt = idx >> 3, nt = idx & 7;
            if (tid == 0) {
                unsigned tgt = 128u * (unsigned)(mt + 1);  // 64*(2mt+2)
                unsigned cur;
                do {
                    asm volatile("ld.acquire.gpu.global.u32 %0, [%1];"
                                 : "=r"(cur) : "l"(&g_step) : "memory");
                } while (cur < tgt);
            }
            __syncthreads();
            xproj_tile(smraw, hA, Wih, bi, bh2, xpo, mt * 128, nt * 128, Hdim);
        }
        return;
    }

    // -------- rnn role ------------------------------------------------------
    const int wid = tid >> 5;
    const int lane = tid & 31;
    const int j0 = bid * 16;

    const uint32_t whbase = smem_u32(smraw + RNN_OFF_W);
    const uint32_t wlbase = whbase + 32768;
    float* p_s = (float*)(smraw + RNN_OFF_S0);

    // load W slice (16 x 1024 fp32) -> bf16 hi/lo swizzled SMEM
    for (int i = tid; i < 4096; i += 256) {
        int j = i >> 8;
        int col4 = i & 255;
        float4 v = *(const float4*)&Whh[(size_t)(j0 + j) * Hdim + col4 * 4];
        __nv_bfloat162 h01 = __floats2bfloat162_rn(v.x, v.y);
        __nv_bfloat162 h23 = __floats2bfloat162_rn(v.z, v.w);
        __nv_bfloat162 l01 = __floats2bfloat162_rn(v.x - __low2float(h01),
                                                   v.y - __high2float(h01));
        __nv_bfloat162 l23 = __floats2bfloat162_rn(v.z - __low2float(h23),
                                                   v.w - __high2float(h23));
        int g = col4 >> 1;
        int off = j * 2048 + ((g ^ (j & 7)) << 4) + (col4 & 1) * 8;
        *(uint2*)(smraw + RNN_OFF_W + off) =
            make_uint2(*(unsigned*)&h01, *(unsigned*)&h23);
        *(uint2*)(smraw + RNN_OFF_W + 32768 + off) =
            make_uint2(*(unsigned*)&l01, *(unsigned*)&l23);
    }
    // zero ALL 16 owned columns of h0 (slot 0)
    if (tid < 64) {
        uint4 z = make_uint4(0, 0, 0, 0);
        *(uint4*)&g_hh[0][(size_t)tid * Hdim + j0] = z;
        *(uint4*)&g_hh[0][(size_t)tid * Hdim + j0 + 8] = z;
        *(uint4*)&g_hl[0][(size_t)tid * Hdim + j0] = z;
        *(uint4*)&g_hl[0][(size_t)tid * Hdim + j0 + 8] = z;
    }
    grid_sync(nrnn + nhelp);

    const int asub = lane >> 3;
    const int arow = (asub & 1) * 8 + (lane & 7);
    const int ack = asub >> 1;
    const int brow = ((lane >> 4) & 1) * 8 + (lane & 7);
    const int bck = (lane >> 3) & 1;
    const int eb = tid >> 2;
    const int ej = (tid & 3) * 4;

#pragma unroll 1
    for (int t = 0; t < Sdim; t++) {
        const __nv_bfloat16* hh_in = g_hh[t & 1];
        const __nv_bfloat16* hl_in = g_hl[t & 1];
        __nv_bfloat16* hh_out = g_hh[(t + 1) & 1];
        __nv_bfloat16* hl_out = g_hl[(t + 1) & 1];

        float4 xpv = *(const float4*)&xp[(size_t)eb * strideB + (size_t)t * strideT
                                         + j0 + ej];

        float acc[4][2][4];
#pragma unroll
        for (int mt = 0; mt < 4; mt++)
#pragma unroll
            for (int nt = 0; nt < 2; nt++)
#pragma unroll
                for (int i = 0; i < 4; i++) acc[mt][nt][i] = 0.0f;

        stage_h2(hh_in, hl_in, 0, smraw + RNN_OFF_S0, tid);
        asm volatile("cp.async.commit_group;");
        stage_h2(hh_in, hl_in, 1, smraw + RNN_OFF_S1, tid);
        asm volatile("cp.async.commit_group;");

#pragma unroll
        for (int c = 0; c < 4; c++) {
            if (c < 3) asm volatile("cp.async.wait_group 1;");
            else       asm volatile("cp.async.wait_group 0;");
            __syncthreads();

            const uint32_t shbase = smem_u32(smraw +
                ((c & 1) ? RNN_OFF_S1 : RNN_OFF_S0));
            const uint32_t slbase = shbase + 32768;

#pragma unroll
            for (int s2 = 0; s2 < 2; s2++) {
                uint32_t ah[4][4], al[4][4];
                int gA = wid * 4 + s2 * 2 + ack;
#pragma unroll
                for (int mt = 0; mt < 4; mt++) {
                    int row = mt * 16 + arow;
                    uint32_t sw = (uint32_t)((gA ^ (row & 7)) << 4);
                    ldsm_x4(shbase + row * 512 + sw, ah[mt]);
                    ldsm_x4(slbase + row * 512 + sw, al[mt]);
                }
                int sg = c * 16 + wid * 2 + s2;
                int gB = sg * 2 + bck;
                uint32_t bh[4], bl[4];
                uint32_t bsw = (uint32_t)((gB ^ (brow & 7)) << 4);
                ldsm_x4(whbase + brow * 2048 + bsw, bh);
                ldsm_x4(wlbase + brow * 2048 + bsw, bl);

#pragma unroll
                for (int mt = 0; mt < 4; mt++) {
                    mma16816(acc[mt][0], ah[mt], &bh[0]);
                    mma16816(acc[mt][1], ah[mt], &bh[2]);
                    mma16816(acc[mt][0], ah[mt], &bl[0]);
                    mma16816(acc[mt][1], ah[mt], &bl[2]);
                    mma16816(acc[mt][0], al[mt], &bh[0]);
                    mma16816(acc[mt][1], al[mt], &bh[2]);
                }
            }
            __syncthreads();
            if (c + 2 < 4) {
                stage_h2(hh_in, hl_in, c + 2,
                         smraw + ((c & 1) ? RNN_OFF_S1 : RNN_OFF_S0), tid);
                asm volatile("cp.async.commit_group;");
            }
        }

        // cross-warp reduce via SMEM partials (alias stage buf 0)
#pragma unroll
        for (int mt = 0; mt < 4; mt++)
#pragma unroll
            for (int nt = 0; nt < 2; nt++) {
                int b = mt * 16 + (lane >> 2);
                int j = nt * 8 + (lane & 3) * 2;
                *(float2*)&p_s[wid * 1024 + b * 16 + j] =
                    make_float2(acc[mt][nt][0], acc[mt][nt][1]);
                *(float2*)&p_s[wid * 1024 + (b + 8) * 16 + j] =
                    make_float2(acc[mt][nt][2], acc[mt][nt][3]);
            }
        __syncthreads();

        {
            int o = tid * 4;
            float4 s = *(const float4*)&p_s[o];
#pragma unroll
            for (int w = 1; w < 8; w++) {
                float4 q = *(const float4*)&p_s[w * 1024 + o];
                s.x += q.x; s.y += q.y; s.z += q.z; s.w += q.w;
            }
            float v0 = tanhf(s.x + xpv.x);
            float v1 = tanhf(s.y + xpv.y);
            float v2 = tanhf(s.z + xpv.z);
            float v3 = tanhf(s.w + xpv.w);

            __nv_bfloat162 h01 = __floats2bfloat162_rn(v0, v1);
            __nv_bfloat162 h23 = __floats2bfloat162_rn(v2, v3);
            __nv_bfloat162 l01 = __floats2bfloat162_rn(v0 - __low2float(h01),
                                                       v1 - __high2float(h01));
            __nv_bfloat162 l23 = __floats2bfloat162_rn(v2 - __low2float(h23),
                                                       v3 - __high2float(h23));
            size_t ho = (size_t)eb * Hdim + j0 + ej;
            *(uint2*)&hh_out[ho] = make_uint2(*(unsigned*)&h01, *(unsigned*)&h23);
            *(uint2*)&hl_out[ho] = make_uint2(*(unsigned*)&l01, *(unsigned*)&l23);
            if (out_seq)
                *(float4*)&out_seq[((size_t)t * Bdim + eb) * Hdim + j0 + ej] =
                    make_float4(v0, v1, v2, v3);
        }

        // publish this CTA's step (layer 0 only; release orders prior stores)
        __syncthreads();
        if (out_seq != nullptr && tid == 0)
            asm volatile("red.release.gpu.global.add.u32 [%0], 1;"
                         :: "l"(&g_step) : "memory");
        grid_sync(nrnn);
    }
}

// ============================================================================
// Final FC + sigmoid: h_last = g_hh[0] + g_hl[0]  ((511+1)&1 = 0)
// ============================================================================
__global__ void fc_kernel(const __nv_bfloat16* __restrict__ hh,
                          const __nv_bfloat16* __restrict__ hl,
                          const float* __restrict__ fcw,
                          const float* __restrict__ fcb,
                          float* __restrict__ out)
{
    __shared__ float red[8];
    int b = blockIdx.x, tid = threadIdx.x;
    float s = 0.0f;
    for (int k = tid; k < Hdim; k += 256) {
        float h = __bfloat162float(hh[b * Hdim + k]) +
                  __bfloat162float(hl[b * Hdim + k]);
        s += h * fcw[k];
    }
#pragma unroll
    for (int o = 16; o; o >>= 1) s += __shfl_xor_sync(0xFFFFFFFFu, s, o);
    if ((tid & 31) == 0) red[tid >> 5] = s;
    __syncthreads();
    if (tid == 0) {
        float tot = 0.0f;
#pragma unroll
        for (int i = 0; i < 8; i++) tot += red[i];
        float logit = tot + fcb[0];
        out[b] = 1.0f / (1.0f + expf(-logit));
    }
}

// ============================================================================
extern "C" void kernel_launch(void* const* d_in, const int* in_sizes, int n_in,
                              void* d_out, int out_size)
{
    const float* x     = (const float*)d_in[0];
    const float* W_ih0 = (const float*)d_in[1];
    const float* W_hh0 = (const float*)d_in[2];
    const float* b_ih0 = (const float*)d_in[3];
    const float* b_hh0 = (const float*)d_in[4];
    const float* W_ih1 = (const float*)d_in[5];
    const float* W_hh1 = (const float*)d_in[6];
    const float* b_ih1 = (const float*)d_in[7];
    const float* b_hh1 = (const float*)d_in[8];
    const float* fc_w  = (const float*)d_in[9];
    const float* fc_b  = (const float*)d_in[10];
    float* out = (float*)d_out;

    float *xp, *xp2, *h1;
    __nv_bfloat16 *hh, *hl;
    cudaGetSymbolAddress((void**)&xp, g_xp);
    cudaGetSymbolAddress((void**)&xp2, g_xp2);
    cudaGetSymbolAddress((void**)&h1, g_h1);
    cudaGetSymbolAddress((void**)&hh, g_hh);
    cudaGetSymbolAddress((void**)&hl, g_hl);

    cudaFuncSetAttribute(rnn_kernel, cudaFuncAttributeMaxDynamicSharedMemorySize,
                         RNN_SMEM_BYTES);
    cudaFuncSetAttribute(xproj_mma_kernel<Fdim>,
                         cudaFuncAttributeMaxDynamicSharedMemorySize, XP_SMEM);

    dim3 xgrid(8, 256);

    // layer-0 xp: rows m = b*S + t -> xp[(b*S+t)*H + j]
    xproj_mma_kernel<Fdim><<<xgrid, 256, XP_SMEM>>>(x, W_ih0, b_ih0, b_hh0, xp);
    // layer-0 rnn (64 CTAs) + xp1 helpers (84 CTAs)
    rnn_kernel<<<148, 256, RNN_SMEM_BYTES>>>(
        xp, W_hh0, h1, (long long)Sdim * Hdim, (long long)Hdim,
        h1, W_ih1, b_ih1, b_hh1, xp2, 64, 84);
    // layer-1 rnn (64 CTAs); xp2 rows m = t*B + b
    rnn_kernel<<<64, 256, RNN_SMEM_BYTES>>>(
        xp2, W_hh1, nullptr, (long long)Hdim, (long long)Bdim * Hdim,
        nullptr, nullptr, nullptr, nullptr, nullptr, 64, 0);
    // head: final h2 in slot 0
    fc_kernel<<<64, 256>>>(hh, hl, fc_w, fc_b, out);
}

// round 11
// speedup vs baseline: 1.7150x; 1.1964x over previous
#include <cuda_runtime.h>
#include <cuda_bf16.h>
#include <math.h>
#include <stdint.h>

#define Bdim 64
#define Sdim 512
#define Fdim 512
#define Hdim 1024

// ---------------- scratch (static device globals; no runtime allocation) ----
__device__ float g_xp[(size_t)Bdim * Sdim * Hdim];    // xp layer 0 (from x)
__device__ float g_xp2[(size_t)Bdim * Sdim * Hdim];   // xp layer 1 [t][b][H] (cohort A)
__device__ __nv_bfloat16 g_hh1[2][Bdim * Hdim];       // layer-0 hidden hi, [b][k]
__device__ __nv_bfloat16 g_hl1[2][Bdim * Hdim];       // layer-0 hidden lo
__device__ __nv_bfloat16 g_hh2[2][Bdim * Hdim];       // layer-1 hidden hi
__device__ __nv_bfloat16 g_hl2[2][Bdim * Hdim];       // layer-1 hidden lo
__device__ unsigned g_barG_cnt = 0; __device__ unsigned g_barG_gen = 0;
__device__ unsigned g_barA_cnt = 0; __device__ unsigned g_barA_gen = 0;
__device__ unsigned g_barB_cnt = 0; __device__ unsigned g_barB_gen = 0;
__device__ unsigned g_stepA = 0;    // A publications: 64 per completed xp2 step

static __device__ __forceinline__ unsigned smem_u32(const void* p) {
    return (unsigned)__cvta_generic_to_shared(p);
}

// ---------------- cohort barrier: scoped release/acquire --------------------
static __device__ __forceinline__ void grid_sync_p(unsigned* cnt, unsigned* gen,
                                                   int nblocks) {
    __syncthreads();
    if (threadIdx.x == 0) {
        unsigned g;
        asm volatile("ld.relaxed.gpu.global.u32 %0, [%1];" : "=r"(g) : "l"(gen));
        unsigned old;
        asm volatile("atom.acq_rel.gpu.global.add.u32 %0, [%1], 1;"
                     : "=r"(old) : "l"(cnt) : "memory");
        if (old == (unsigned)(nblocks - 1)) {
            asm volatile("st.relaxed.gpu.global.u32 [%0], %1;"
                         :: "l"(cnt), "r"(0u) : "memory");
            asm volatile("st.release.gpu.global.u32 [%0], %1;"
                         :: "l"(gen), "r"(g + 1) : "memory");
        } else {
            unsigned cur;
            do {
                asm volatile("ld.acquire.gpu.global.u32 %0, [%1];"
                             : "=r"(cur) : "l"(gen) : "memory");
            } while (cur == g);
        }
    }
    __syncthreads();
}

// ---------------- mma.sync helpers ------------------------------------------
static __device__ __forceinline__ void ldsm_x4(uint32_t addr, uint32_t* r) {
    asm volatile("ldmatrix.sync.aligned.m8n8.x4.shared.b16 {%0,%1,%2,%3}, [%4];"
                 : "=r"(r[0]), "=r"(r[1]), "=r"(r[2]), "=r"(r[3]) : "r"(addr));
}
static __device__ __forceinline__ void mma16816(float* c, const uint32_t* a,
                                                const uint32_t* b) {
    asm volatile("mma.sync.aligned.m16n8k16.row.col.f32.bf16.bf16.f32 "
                 "{%0,%1,%2,%3}, {%4,%5,%6,%7}, {%8,%9}, {%0,%1,%2,%3};"
                 : "+f"(c[0]), "+f"(c[1]), "+f"(c[2]), "+f"(c[3])
                 : "r"(a[0]), "r"(a[1]), "r"(a[2]), "r"(a[3]),
                   "r"(b[0]), "r"(b[1]));
}
static __device__ __forceinline__ void split_bf16(float4 v, uint2& hi, uint2& lo) {
    __nv_bfloat162 h01 = __floats2bfloat162_rn(v.x, v.y);
    __nv_bfloat162 h23 = __floats2bfloat162_rn(v.z, v.w);
    __nv_bfloat162 l01 = __floats2bfloat162_rn(v.x - __low2float(h01),
                                               v.y - __high2float(h01));
    __nv_bfloat162 l23 = __floats2bfloat162_rn(v.z - __low2float(h23),
                                               v.w - __high2float(h23));
    hi = make_uint2(*(unsigned*)&h01, *(unsigned*)&h23);
    lo = make_uint2(*(unsigned*)&l01, *(unsigned*)&l23);
}

// ============================================================================
// xproj kernel for layer-0 xp (proven R7 body): out = A@Wt^T + ba + bb
// ============================================================================
#define SW128(o) ((o) ^ (((o) >> 3) & 0x70))
#define XP_OFF_BIAS 0
#define XP_OFF_AH   1024
#define XP_OFF_AL   (XP_OFF_AH + 16384)
#define XP_OFF_BH   (XP_OFF_AL + 16384)
#define XP_OFF_BL   (XP_OFF_BH + 16384)
#define XP_SMEM     (XP_OFF_BL + 16384)

static __device__ __forceinline__ uint32_t lm_addr(uint32_t base, int r, int ck) {
    return base + r * 128 + ((ck ^ (r & 7)) << 4);
}

template <int K>
__global__ void __launch_bounds__(256, 2) xproj_mma_kernel(
    const float* __restrict__ A, const float* __restrict__ Wt,
    const float* __restrict__ ba, const float* __restrict__ bb,
    float* __restrict__ out)
{
    extern __shared__ __align__(1024) char xsm[];
    const uint32_t sb = smem_u32(xsm);
    const int tid = threadIdx.x;
    const int wid = tid >> 5;
    const int lane = tid & 31;
    const int wm = wid & 3;
    const int wn = wid >> 2;
    const int m0 = blockIdx.y * 128;
    const int n0 = blockIdx.x * 128;

    float* sbias = (float*)(xsm + XP_OFF_BIAS);
    if (tid < 128) sbias[tid] = ba[n0 + tid] + bb[n0 + tid];

    float acc[2][8][4];
#pragma unroll
    for (int mt = 0; mt < 2; mt++)
#pragma unroll
        for (int nt = 0; nt < 8; nt++)
#pragma unroll
            for (int i = 0; i < 4; i++) acc[mt][nt][i] = 0.0f;

    const int NKT = K / 64;
#pragma unroll 1
    for (int kt = 0; kt < NKT; kt++) {
        __syncthreads();
        const float* Asrc = A + (size_t)m0 * K + kt * 64;
        const float* Bsrc = Wt + (size_t)n0 * K + kt * 64;
#pragma unroll
        for (int r = 0; r < 8; r++) {
            int idx = r * 256 + tid;
            int row = idx >> 4;
            int c4 = idx & 15;
            int sw = SW128(row * 128 + c4 * 8);
            uint2 hi, lo;
            split_bf16(*(const float4*)&Asrc[(size_t)row * K + c4 * 4], hi, lo);
            *(uint2*)(xsm + XP_OFF_AH + sw) = hi;
            *(uint2*)(xsm + XP_OFF_AL + sw) = lo;
            split_bf16(*(const float4*)&Bsrc[(size_t)row * K + c4 * 4], hi, lo);
            *(uint2*)(xsm + XP_OFF_BH + sw) = hi;
            *(uint2*)(xsm + XP_OFF_BL + sw) = lo;
        }
        __syncthreads();

        const int asub = lane >> 3;
        const int arow = (asub & 1) * 8 + (lane & 7);
        const int ack = asub >> 1;
        const int brow = ((lane >> 4) & 1) * 8 + (lane & 7);
        const int bck = (lane >> 3) & 1;

#pragma unroll
        for (int p = 0; p < 3; p++) {
            uint32_t aBase = sb + ((p == 2) ? XP_OFF_AL : XP_OFF_AH);
            uint32_t bBase = sb + ((p == 1) ? XP_OFF_BL : XP_OFF_BH);
#pragma unroll
            for (int kk = 0; kk < 4; kk++) {
                uint32_t afrag[2][4], bfrag[8][2];
#pragma unroll
                for (int mt = 0; mt < 2; mt++)
                    ldsm_x4(lm_addr(aBase, wm * 32 + mt * 16 + arow, kk * 2 + ack),
                            afrag[mt]);
#pragma unroll
                for (int np = 0; np < 4; np++) {
                    uint32_t r4[4];
                    ldsm_x4(lm_addr(bBase, wn * 64 + np * 16 + brow, kk * 2 + bck), r4);
                    bfrag[np * 2][0] = r4[0]; bfrag[np * 2][1] = r4[1];
                    bfrag[np * 2 + 1][0] = r4[2]; bfrag[np * 2 + 1][1] = r4[3];
                }
#pragma unroll
                for (int mt = 0; mt < 2; mt++)
#pragma unroll
                    for (int nt = 0; nt < 8; nt++)
                        mma16816(acc[mt][nt], afrag[mt], bfrag[nt]);
            }
        }
    }

#pragma unroll
    for (int mt = 0; mt < 2; mt++) {
#pragma unroll
        for (int nt = 0; nt < 8; nt++) {
            int m = m0 + wm * 32 + mt * 16 + (lane >> 2);
            int nl = wn * 64 + nt * 8 + (lane & 3) * 2;
            float2 o0, o1;
            o0.x = acc[mt][nt][0] + sbias[nl];
            o0.y = acc[mt][nt][1] + sbias[nl + 1];
            o1.x = acc[mt][nt][2] + sbias[nl];
            o1.y = acc[mt][nt][3] + sbias[nl + 1];
            *(float2*)&out[(size_t)m * Hdim + n0 + nl] = o0;
            *(float2*)&out[(size_t)(m + 8) * Hdim + n0 + nl] = o1;
        }
    }
}

// ============================================================================
// Fused dual-layer recurrence, one persistent kernel, 128 CTAs x 256 threads.
// Cohort A (bid 0..63): layer-0 rec (16 j) + inline xp2 (16 cols), n=32 MMA.
//   SMEM: W 128KB (32 rows x 1024 hi/lo) | 2 stage bufs x 32KB (128-k chunks).
// Cohort B (bid 64..127): layer-1 rec (16 j), R8-proven body, gated on g_stepA.
//   SMEM: W 64KB | 2 stage bufs x 64KB (256-k chunks).
// ============================================================================
#define RNN_SMEM_BYTES 196608
// cohort A offsets
#define A_OFF_WH 0
#define A_OFF_WL 65536
#define A_OFF_S0 131072
#define A_OFF_S1 163840
// cohort B offsets
#define B_OFF_W  0
#define B_OFF_S0 65536
#define B_OFF_S1 131072

// ---- cohort A staging: chunk c = 128 k-values, rows = b (256B), hi+lo ------
static __device__ __forceinline__ void stage_hA(
    const __nv_bfloat16* __restrict__ hh, const __nv_bfloat16* __restrict__ hl,
    int c, char* dst, int tid)
{
#pragma unroll
    for (int r = 0; r < 4; r++) {
        int idx = r * 256 + tid;              // 0..1023
        int b = idx >> 4;                     // 0..63
        int g = idx & 15;                     // granule within 256B row
        int ph = (g & 8) | ((g ^ (b & 7)) & 7);
        uint32_t d = smem_u32(dst + b * 256 + ph * 16);
        const __nv_bfloat16* s = hh + b * Hdim + c * 128 + g * 8;
        asm volatile("cp.async.cg.shared.global [%0], [%1], 16;" ::"r"(d), "l"(s));
        const __nv_bfloat16* s2 = hl + b * Hdim + c * 128 + g * 8;
        asm volatile("cp.async.cg.shared.global [%0], [%1], 16;"
                     ::"r"(d + 16384), "l"(s2));
    }
}

// ---- cohort B staging: chunk kc = 256 k-values, rows = b (512B), hi+lo -----
static __device__ __forceinline__ void stage_hB(
    const __nv_bfloat16* __restrict__ hh, const __nv_bfloat16* __restrict__ hl,
    int kc, char* dst, int tid)
{
#pragma unroll
    for (int r = 0; r < 8; r++) {
        int idx = r * 256 + tid;
        int b = idx >> 5;
        int lg = idx & 31;
        uint32_t d = smem_u32(dst + b * 512 + ((lg ^ (b & 7)) << 4));
        const __nv_bfloat16* s = hh + b * Hdim + kc * 256 + lg * 8;
        asm volatile("cp.async.cg.shared.global [%0], [%1], 16;" ::"r"(d), "l"(s));
        const __nv_bfloat16* s2 = hl + b * Hdim + kc * 256 + lg * 8;
        asm volatile("cp.async.cg.shared.global [%0], [%1], 16;"
                     ::"r"(d + 32768), "l"(s2));
    }
}

__global__ void __launch_bounds__(256) rnn_fused_kernel(
    const float* __restrict__ xp0, const float* __restrict__ Whh0,
    const float* __restrict__ Wih1, const float* __restrict__ bi1,
    const float* __restrict__ bh1, const float* __restrict__ Whh1,
    float* __restrict__ xp2)
{
    extern __shared__ __align__(1024) char smraw[];
    const int tid = threadIdx.x;
    const int bid = blockIdx.x;
    const int wid = tid >> 5;
    const int lane = tid & 31;

    if (bid == 0 && tid == 0)
        asm volatile("st.relaxed.gpu.global.u32 [%0], %1;"
                     :: "l"(&g_stepA), "r"(0u) : "memory");

    // common ldmatrix lane mappings
    const int asub = lane >> 3;
    const int arow = (asub & 1) * 8 + (lane & 7);
    const int ack = asub >> 1;
    const int brow = ((lane >> 4) & 1) * 8 + (lane & 7);
    const int bck = (lane >> 3) & 1;
    const int eb = tid >> 2;
    const int ej = (tid & 3) * 4;

    if (bid < 64) {
        // ==================== Cohort A: layer-0 rec + xp2 ====================
        const int j0 = bid * 16;
        const uint32_t whb = smem_u32(smraw + A_OFF_WH);
        const uint32_t wlb = smem_u32(smraw + A_OFF_WL);
        float* p_s = (float*)(smraw + A_OFF_S0);   // partials alias (16K floats)

        // W: rows 0..15 = Whh0[j0+j], rows 16..31 = Wih1[j0+j]; hi/lo swizzled
        for (int i = tid; i < 8192; i += 256) {
            int row = i >> 8;                      // 0..31
            int col4 = i & 255;
            const float* src = (row < 16)
                ? &Whh0[(size_t)(j0 + row) * Hdim + col4 * 4]
                : &Wih1[(size_t)(j0 + row - 16) * Hdim + col4 * 4];
            uint2 hi, lo;
            split_bf16(*(const float4*)src, hi, lo);
            int g = col4 >> 1;
            int off = row * 2048 + ((g ^ (row & 7)) << 4) + (col4 & 1) * 8;
            *(uint2*)(smraw + A_OFF_WH + off) = hi;
            *(uint2*)(smraw + A_OFF_WL + off) = lo;
        }
        // zero h1 slot 0 (owned 16 columns)
        if (tid < 64) {
            uint4 z = make_uint4(0, 0, 0, 0);
            *(uint4*)&g_hh1[0][(size_t)tid * Hdim + j0] = z;
            *(uint4*)&g_hh1[0][(size_t)tid * Hdim + j0 + 8] = z;
            *(uint4*)&g_hl1[0][(size_t)tid * Hdim + j0] = z;
            *(uint4*)&g_hl1[0][(size_t)tid * Hdim + j0 + 8] = z;
        }
        // xp2 bias for this thread's 4 columns
        float bias2[4];
#pragma unroll
        for (int i = 0; i < 4; i++)
            bias2[i] = bi1[j0 + ej + i] + bh1[j0 + ej + i];

        grid_sync_p(&g_barG_cnt, &g_barG_gen, 128);

#pragma unroll 1
        for (int s = 0; s <= Sdim; s++) {
            const __nv_bfloat16* hh_in = g_hh1[s & 1];
            const __nv_bfloat16* hl_in = g_hl1[s & 1];
            __nv_bfloat16* hh_out = g_hh1[(s + 1) & 1];
            __nv_bfloat16* hl_out = g_hl1[(s + 1) & 1];

            int tt = (s < Sdim) ? s : Sdim - 1;
            float4 xpv = *(const float4*)&xp0[((size_t)eb * Sdim + tt) * Hdim
                                              + j0 + ej];

            float accR[4][2][4], accX[4][2][4];
#pragma unroll
            for (int mt = 0; mt < 4; mt++)
#pragma unroll
                for (int nt = 0; nt < 2; nt++)
#pragma unroll
                    for (int i = 0; i < 4; i++) {
                        accR[mt][nt][i] = 0.0f;
                        accX[mt][nt][i] = 0.0f;
                    }

            stage_hA(hh_in, hl_in, 0, smraw + A_OFF_S0, tid);
            asm volatile("cp.async.commit_group;");
            stage_hA(hh_in, hl_in, 1, smraw + A_OFF_S1, tid);
            asm volatile("cp.async.commit_group;");

#pragma unroll 1
            for (int c = 0; c < 8; c++) {
                if (c < 7) asm volatile("cp.async.wait_group 1;");
                else       asm volatile("cp.async.wait_group 0;");
                __syncthreads();

                const uint32_t shb = smem_u32(smraw +
                    ((c & 1) ? A_OFF_S1 : A_OFF_S0));
                const uint32_t slb = shb + 16384;

                uint32_t ah[4][4], al[4][4];
                int gA = wid * 2 + ack;
#pragma unroll
                for (int mt = 0; mt < 4; mt++) {
                    int row = mt * 16 + arow;
                    uint32_t ph = (uint32_t)((gA & 8) | ((gA ^ (row & 7)) & 7)) << 4;
                    ldsm_x4(shb + row * 256 + ph, ah[mt]);
                    ldsm_x4(slb + row * 256 + ph, al[mt]);
                }
                int sg = c * 8 + wid;
                int gB = sg * 2 + bck;
                uint32_t bsw = (uint32_t)((gB ^ (brow & 7)) << 4);
                uint32_t bh[4], bl[4], ch[4], cl[4];
                ldsm_x4(whb + brow * 2048 + bsw, bh);
                ldsm_x4(wlb + brow * 2048 + bsw, bl);
                ldsm_x4(whb + (16 + brow) * 2048 + bsw, ch);
                ldsm_x4(wlb + (16 + brow) * 2048 + bsw, cl);

#pragma unroll
                for (int mt = 0; mt < 4; mt++) {
                    mma16816(accR[mt][0], ah[mt], &bh[0]);
                    mma16816(accR[mt][1], ah[mt], &bh[2]);
                    mma16816(accR[mt][0], ah[mt], &bl[0]);
                    mma16816(accR[mt][1], ah[mt], &bl[2]);
                    mma16816(accR[mt][0], al[mt], &bh[0]);
                    mma16816(accR[mt][1], al[mt], &bh[2]);
                    mma16816(accX[mt][0], ah[mt], &ch[0]);
                    mma16816(accX[mt][1], ah[mt], &ch[2]);
                    mma16816(accX[mt][0], ah[mt], &cl[0]);
                    mma16816(accX[mt][1], ah[mt], &cl[2]);
                    mma16816(accX[mt][0], al[mt], &ch[0]);
                    mma16816(accX[mt][1], al[mt], &ch[2]);
                }
                __syncthreads();
                if (c + 2 < 8) {
                    stage_hA(hh_in, hl_in, c + 2,
                             smraw + ((c & 1) ? A_OFF_S1 : A_OFF_S0), tid);
                    asm volatile("cp.async.commit_group;");
                }
            }

            // partials: rec -> [0,8192), xp2 -> [8192,16384)
#pragma unroll
            for (int mt = 0; mt < 4; mt++)
#pragma unroll
                for (int nt = 0; nt < 2; nt++) {
                    int b = mt * 16 + (lane >> 2);
                    int j = nt * 8 + (lane & 3) * 2;
                    *(float2*)&p_s[wid * 1024 + b * 16 + j] =
                        make_float2(accR[mt][nt][0], accR[mt][nt][1]);
                    *(float2*)&p_s[wid * 1024 + (b + 8) * 16 + j] =
                        make_float2(accR[mt][nt][2], accR[mt][nt][3]);
                    *(float2*)&p_s[8192 + wid * 1024 + b * 16 + j] =
                        make_float2(accX[mt][nt][0], accX[mt][nt][1]);
                    *(float2*)&p_s[8192 + wid * 1024 + (b + 8) * 16 + j] =
                        make_float2(accX[mt][nt][2], accX[mt][nt][3]);
                }
            __syncthreads();

            {
                int o = tid * 4;
                float4 sr = *(const float4*)&p_s[o];
                float4 sx = *(const float4*)&p_s[8192 + o];
#pragma unroll
                for (int w = 1; w < 8; w++) {
                    float4 q = *(const float4*)&p_s[w * 1024 + o];
                    sr.x += q.x; sr.y += q.y; sr.z += q.z; sr.w += q.w;
                    float4 q2 = *(const float4*)&p_s[8192 + w * 1024 + o];
                    sx.x += q2.x; sx.y += q2.y; sx.z += q2.z; sx.w += q2.w;
                }
                if (s < Sdim) {
                    float v0 = tanhf(sr.x + xpv.x);
                    float v1 = tanhf(sr.y + xpv.y);
                    float v2 = tanhf(sr.z + xpv.z);
                    float v3 = tanhf(sr.w + xpv.w);
                    uint2 hi, lo;
                    split_bf16(make_float4(v0, v1, v2, v3), hi, lo);
                    size_t ho = (size_t)eb * Hdim + j0 + ej;
                    *(uint2*)&hh_out[ho] = hi;
                    *(uint2*)&hl_out[ho] = lo;
                }
                if (s >= 1) {
                    float4 o4;
                    o4.x = sx.x + bias2[0];
                    o4.y = sx.y + bias2[1];
                    o4.z = sx.z + bias2[2];
                    o4.w = sx.w + bias2[3];
                    *(float4*)&xp2[((size_t)(s - 1) * Bdim + eb) * Hdim + j0 + ej]
                        = o4;
                }
            }
            __syncthreads();
            if (s >= 1 && tid == 0)
                asm volatile("red.release.gpu.global.add.u32 [%0], 1;"
                             :: "l"(&g_stepA) : "memory");
            if (s < Sdim) grid_sync_p(&g_barA_cnt, &g_barA_gen, 64);
        }
    } else {
        // ==================== Cohort B: layer-1 recurrence ====================
        const int j0 = (bid - 64) * 16;
        const uint32_t whb = smem_u32(smraw + B_OFF_W);
        const uint32_t wlb = whb + 32768;
        float* p_s = (float*)(smraw + B_OFF_S0);

        for (int i = tid; i < 4096; i += 256) {
            int j = i >> 8;
            int col4 = i & 255;
            uint2 hi, lo;
            split_bf16(*(const float4*)&Whh1[(size_t)(j0 + j) * Hdim + col4 * 4],
                       hi, lo);
            int g = col4 >> 1;
            int off = j * 2048 + ((g ^ (j & 7)) << 4) + (col4 & 1) * 8;
            *(uint2*)(smraw + B_OFF_W + off) = hi;
            *(uint2*)(smraw + B_OFF_W + 32768 + off) = lo;
        }
        if (tid < 64) {
            uint4 z = make_uint4(0, 0, 0, 0);
            *(uint4*)&g_hh2[0][(size_t)tid * Hdim + j0] = z;
            *(uint4*)&g_hh2[0][(size_t)tid * Hdim + j0 + 8] = z;
            *(uint4*)&g_hl2[0][(size_t)tid * Hdim + j0] = z;
            *(uint4*)&g_hl2[0][(size_t)tid * Hdim + j0 + 8] = z;
        }
        grid_sync_p(&g_barG_cnt, &g_barG_gen, 128);

#pragma unroll 1
        for (int t = 0; t < Sdim; t++) {
            // gate: xp2[t] published by cohort A (count = 64*(t+1))
            if (tid == 0) {
                unsigned tgt = 64u * (unsigned)(t + 1);
                unsigned cur;
                do {
                    asm volatile("ld.acquire.gpu.global.u32 %0, [%1];"
                                 : "=r"(cur) : "l"(&g_stepA) : "memory");
                } while (cur < tgt);
            }
            __syncthreads();

            const __nv_bfloat16* hh_in = g_hh2[t & 1];
            const __nv_bfloat16* hl_in = g_hl2[t & 1];
            __nv_bfloat16* hh_out = g_hh2[(t + 1) & 1];
            __nv_bfloat16* hl_out = g_hl2[(t + 1) & 1];

            float4 xpv = *(const float4*)&xp2[((size_t)t * Bdim + eb) * Hdim
                                              + j0 + ej];

            float acc[4][2][4];
#pragma unroll
            for (int mt = 0; mt < 4; mt++)
#pragma unroll
                for (int nt = 0; nt < 2; nt++)
#pragma unroll
                    for (int i = 0; i < 4; i++) acc[mt][nt][i] = 0.0f;

            stage_hB(hh_in, hl_in, 0, smraw + B_OFF_S0, tid);
            asm volatile("cp.async.commit_group;");
            stage_hB(hh_in, hl_in, 1, smraw + B_OFF_S1, tid);
            asm volatile("cp.async.commit_group;");

#pragma unroll
            for (int c = 0; c < 4; c++) {
                if (c < 3) asm volatile("cp.async.wait_group 1;");
                else       asm volatile("cp.async.wait_group 0;");
                __syncthreads();

                const uint32_t shb = smem_u32(smraw +
                    ((c & 1) ? B_OFF_S1 : B_OFF_S0));
                const uint32_t slb = shb + 32768;

#pragma unroll
                for (int s2 = 0; s2 < 2; s2++) {
                    uint32_t ah[4][4], al[4][4];
                    int gA = wid * 4 + s2 * 2 + ack;
#pragma unroll
                    for (int mt = 0; mt < 4; mt++) {
                        int row = mt * 16 + arow;
                        uint32_t sw = (uint32_t)((gA ^ (row & 7)) << 4);
                        ldsm_x4(shb + row * 512 + sw, ah[mt]);
                        ldsm_x4(slb + row * 512 + sw, al[mt]);
                    }
                    int sg = c * 16 + wid * 2 + s2;
                    int gB = sg * 2 + bck;
                    uint32_t bh[4], bl[4];
                    uint32_t bsw = (uint32_t)((gB ^ (brow & 7)) << 4);
                    ldsm_x4(whb + brow * 2048 + bsw, bh);
                    ldsm_x4(wlb + brow * 2048 + bsw, bl);

#pragma unroll
                    for (int mt = 0; mt < 4; mt++) {
                        mma16816(acc[mt][0], ah[mt], &bh[0]);
                        mma16816(acc[mt][1], ah[mt], &bh[2]);
                        mma16816(acc[mt][0], ah[mt], &bl[0]);
                        mma16816(acc[mt][1], ah[mt], &bl[2]);
                        mma16816(acc[mt][0], al[mt], &bh[0]);
                        mma16816(acc[mt][1], al[mt], &bh[2]);
                    }
                }
                __syncthreads();
                if (c + 2 < 4) {
                    stage_hB(hh_in, hl_in, c + 2,
                             smraw + ((c & 1) ? B_OFF_S1 : B_OFF_S0), tid);
                    asm volatile("cp.async.commit_group;");
                }
            }

#pragma unroll
            for (int mt = 0; mt < 4; mt++)
#pragma unroll
                for (int nt = 0; nt < 2; nt++) {
                    int b = mt * 16 + (lane >> 2);
                    int j = nt * 8 + (lane & 3) * 2;
                    *(float2*)&p_s[wid * 1024 + b * 16 + j] =
                        make_float2(acc[mt][nt][0], acc[mt][nt][1]);
                    *(float2*)&p_s[wid * 1024 + (b + 8) * 16 + j] =
                        make_float2(acc[mt][nt][2], acc[mt][nt][3]);
                }
            __syncthreads();

            {
                int o = tid * 4;
                float4 s = *(const float4*)&p_s[o];
#pragma unroll
                for (int w = 1; w < 8; w++) {
                    float4 q = *(const float4*)&p_s[w * 1024 + o];
                    s.x += q.x; s.y += q.y; s.z += q.z; s.w += q.w;
                }
                float v0 = tanhf(s.x + xpv.x);
                float v1 = tanhf(s.y + xpv.y);
                float v2 = tanhf(s.z + xpv.z);
                float v3 = tanhf(s.w + xpv.w);
                uint2 hi, lo;
                split_bf16(make_float4(v0, v1, v2, v3), hi, lo);
                size_t ho = (size_t)eb * Hdim + j0 + ej;
                *(uint2*)&hh_out[ho] = hi;
                *(uint2*)&hl_out[ho] = lo;
            }
            grid_sync_p(&g_barB_cnt, &g_barB_gen, 64);
        }
    }
}

// ============================================================================
// Final FC + sigmoid: h_last = g_hh2[0] + g_hl2[0]  ((511+1)&1 = 0)
// ============================================================================
__global__ void fc_kernel(const __nv_bfloat16* __restrict__ hh,
                          const __nv_bfloat16* __restrict__ hl,
                          const float* __restrict__ fcw,
                          const float* __restrict__ fcb,
                          float* __restrict__ out)
{
    __shared__ float red[8];
    int b = blockIdx.x, tid = threadIdx.x;
    float s = 0.0f;
    for (int k = tid; k < Hdim; k += 256) {
        float h = __bfloat162float(hh[b * Hdim + k]) +
                  __bfloat162float(hl[b * Hdim + k]);
        s += h * fcw[k];
    }
#pragma unroll
    for (int o = 16; o; o >>= 1) s += __shfl_xor_sync(0xFFFFFFFFu, s, o);
    if ((tid & 31) == 0) red[tid >> 5] = s;
    __syncthreads();
    if (tid == 0) {
        float tot = 0.0f;
#pragma unroll
        for (int i = 0; i < 8; i++) tot += red[i];
        float logit = tot + fcb[0];
        out[b] = 1.0f / (1.0f + expf(-logit));
    }
}

// ============================================================================
extern "C" void kernel_launch(void* const* d_in, const int* in_sizes, int n_in,
                              void* d_out, int out_size)
{
    const float* x     = (const float*)d_in[0];
    const float* W_ih0 = (const float*)d_in[1];
    const float* W_hh0 = (const float*)d_in[2];
    const float* b_ih0 = (const float*)d_in[3];
    const float* b_hh0 = (const float*)d_in[4];
    const float* W_ih1 = (const float*)d_in[5];
    const float* W_hh1 = (const float*)d_in[6];
    const float* b_ih1 = (const float*)d_in[7];
    const float* b_hh1 = (const float*)d_in[8];
    const float* fc_w  = (const float*)d_in[9];
    const float* fc_b  = (const float*)d_in[10];
    float* out = (float*)d_out;

    float *xp, *xp2;
    __nv_bfloat16 *hh2, *hl2;
    cudaGetSymbolAddress((void**)&xp, g_xp);
    cudaGetSymbolAddress((void**)&xp2, g_xp2);
    cudaGetSymbolAddress((void**)&hh2, g_hh2);
    cudaGetSymbolAddress((void**)&hl2, g_hl2);

    cudaFuncSetAttribute(rnn_fused_kernel,
                         cudaFuncAttributeMaxDynamicSharedMemorySize,
                         RNN_SMEM_BYTES);
    cudaFuncSetAttribute(xproj_mma_kernel<Fdim>,
                         cudaFuncAttributeMaxDynamicSharedMemorySize, XP_SMEM);

    dim3 xgrid(8, 256);
    // layer-0 xp: rows m = b*S + t -> xp[(b*S+t)*H + j]
    xproj_mma_kernel<Fdim><<<xgrid, 256, XP_SMEM>>>(x, W_ih0, b_ih0, b_hh0, xp);
    // fused dual-layer recurrence (cohort A: rec0 + xp2; cohort B: rec1)
    rnn_fused_kernel<<<128, 256, RNN_SMEM_BYTES>>>(
        xp, W_hh0, W_ih1, b_ih1, b_hh1, W_hh1, xp2);
    // head: final h2 in slot 0
    fc_kernel<<<64, 256>>>(hh2, hl2, fc_w, fc_b, out);
}

// round 12
// speedup vs baseline: 1.9401x; 1.1313x over previous
#include <cuda_runtime.h>
#include <cuda_bf16.h>
#include <math.h>
#include <stdint.h>

#define Bdim 64
#define Sdim 512
#define Fdim 512
#define Hdim 1024

// ---------------- scratch (static device globals; no runtime allocation) ----
__device__ float g_xp[(size_t)Bdim * Sdim * Hdim];    // xp layer 0 (from x)
__device__ float g_xp2[(size_t)Bdim * Sdim * Hdim];   // xp layer 1 [t][b][H]
__device__ __nv_bfloat16 g_hh1[2][Bdim * Hdim];       // layer-0 hidden hi, [b][k]
__device__ __nv_bfloat16 g_hl1[2][Bdim * Hdim];       // layer-0 hidden lo
__device__ __nv_bfloat16 g_hh2[2][Bdim * Hdim];       // layer-1 hidden hi
__device__ __nv_bfloat16 g_hl2[2][Bdim * Hdim];       // layer-1 hidden lo
__device__ unsigned g_barG_cnt = 0; __device__ unsigned g_barG_gen = 0;
__device__ unsigned g_barA_cnt = 0; __device__ unsigned g_barA_gen = 0;
__device__ unsigned g_barB_cnt = 0; __device__ unsigned g_barB_gen = 0;
__device__ unsigned g_stepA = 0;    // A publications: 64 per completed xp2 step

static __device__ __forceinline__ unsigned smem_u32(const void* p) {
    return (unsigned)__cvta_generic_to_shared(p);
}

// ---------------- cohort barrier: scoped release/acquire --------------------
static __device__ __forceinline__ void grid_sync_p(unsigned* cnt, unsigned* gen,
                                                   int nblocks) {
    __syncthreads();
    if (threadIdx.x == 0) {
        unsigned g;
        asm volatile("ld.relaxed.gpu.global.u32 %0, [%1];" : "=r"(g) : "l"(gen));
        unsigned old;
        asm volatile("atom.acq_rel.gpu.global.add.u32 %0, [%1], 1;"
                     : "=r"(old) : "l"(cnt) : "memory");
        if (old == (unsigned)(nblocks - 1)) {
            asm volatile("st.relaxed.gpu.global.u32 [%0], %1;"
                         :: "l"(cnt), "r"(0u) : "memory");
            asm volatile("st.release.gpu.global.u32 [%0], %1;"
                         :: "l"(gen), "r"(g + 1) : "memory");
        } else {
            unsigned cur;
            do {
                asm volatile("ld.acquire.gpu.global.u32 %0, [%1];"
                             : "=r"(cur) : "l"(gen) : "memory");
            } while (cur == g);
        }
    }
    __syncthreads();
}

// ---------------- mma.sync helpers ------------------------------------------
static __device__ __forceinline__ void ldsm_x4(uint32_t addr, uint32_t* r) {
    asm volatile("ldmatrix.sync.aligned.m8n8.x4.shared.b16 {%0,%1,%2,%3}, [%4];"
                 : "=r"(r[0]), "=r"(r[1]), "=r"(r[2]), "=r"(r[3]) : "r"(addr));
}
static __device__ __forceinline__ void mma16816(float* c, const uint32_t* a,
                                                const uint32_t* b) {
    asm volatile("mma.sync.aligned.m16n8k16.row.col.f32.bf16.bf16.f32 "
                 "{%0,%1,%2,%3}, {%4,%5,%6,%7}, {%8,%9}, {%0,%1,%2,%3};"
                 : "+f"(c[0]), "+f"(c[1]), "+f"(c[2]), "+f"(c[3])
                 : "r"(a[0]), "r"(a[1]), "r"(a[2]), "r"(a[3]),
                   "r"(b[0]), "r"(b[1]));
}
static __device__ __forceinline__ void split_bf16(float4 v, uint2& hi, uint2& lo) {
    __nv_bfloat162 h01 = __floats2bfloat162_rn(v.x, v.y);
    __nv_bfloat162 h23 = __floats2bfloat162_rn(v.z, v.w);
    __nv_bfloat162 l01 = __floats2bfloat162_rn(v.x - __low2float(h01),
                                               v.y - __high2float(h01));
    __nv_bfloat162 l23 = __floats2bfloat162_rn(v.z - __low2float(h23),
                                               v.w - __high2float(h23));
    hi = make_uint2(*(unsigned*)&h01, *(unsigned*)&h23);
    lo = make_uint2(*(unsigned*)&l01, *(unsigned*)&l23);
}

// ============================================================================
// xproj kernel for layer-0 xp (proven R7 body): out = A@Wt^T + ba + bb
// ============================================================================
#define SW128(o) ((o) ^ (((o) >> 3) & 0x70))
#define XP_OFF_BIAS 0
#define XP_OFF_AH   1024
#define XP_OFF_AL   (XP_OFF_AH + 16384)
#define XP_OFF_BH   (XP_OFF_AL + 16384)
#define XP_OFF_BL   (XP_OFF_BH + 16384)
#define XP_SMEM     (XP_OFF_BL + 16384)

static __device__ __forceinline__ uint32_t lm_addr(uint32_t base, int r, int ck) {
    return base + r * 128 + ((ck ^ (r & 7)) << 4);
}

template <int K>
__global__ void __launch_bounds__(256, 2) xproj_mma_kernel(
    const float* __restrict__ A, const float* __restrict__ Wt,
    const float* __restrict__ ba, const float* __restrict__ bb,
    float* __restrict__ out)
{
    extern __shared__ __align__(1024) char xsm[];
    const uint32_t sb = smem_u32(xsm);
    const int tid = threadIdx.x;
    const int wid = tid >> 5;
    const int lane = tid & 31;
    const int wm = wid & 3;
    const int wn = wid >> 2;
    const int m0 = blockIdx.y * 128;
    const int n0 = blockIdx.x * 128;

    float* sbias = (float*)(xsm + XP_OFF_BIAS);
    if (tid < 128) sbias[tid] = ba[n0 + tid] + bb[n0 + tid];

    float acc[2][8][4];
#pragma unroll
    for (int mt = 0; mt < 2; mt++)
#pragma unroll
        for (int nt = 0; nt < 8; nt++)
#pragma unroll
            for (int i = 0; i < 4; i++) acc[mt][nt][i] = 0.0f;

    const int NKT = K / 64;
#pragma unroll 1
    for (int kt = 0; kt < NKT; kt++) {
        __syncthreads();
        const float* Asrc = A + (size_t)m0 * K + kt * 64;
        const float* Bsrc = Wt + (size_t)n0 * K + kt * 64;
#pragma unroll
        for (int r = 0; r < 8; r++) {
            int idx = r * 256 + tid;
            int row = idx >> 4;
            int c4 = idx & 15;
            int sw = SW128(row * 128 + c4 * 8);
            uint2 hi, lo;
            split_bf16(*(const float4*)&Asrc[(size_t)row * K + c4 * 4], hi, lo);
            *(uint2*)(xsm + XP_OFF_AH + sw) = hi;
            *(uint2*)(xsm + XP_OFF_AL + sw) = lo;
            split_bf16(*(const float4*)&Bsrc[(size_t)row * K + c4 * 4], hi, lo);
            *(uint2*)(xsm + XP_OFF_BH + sw) = hi;
            *(uint2*)(xsm + XP_OFF_BL + sw) = lo;
        }
        __syncthreads();

        const int asub = lane >> 3;
        const int arow = (asub & 1) * 8 + (lane & 7);
        const int ack = asub >> 1;
        const int brow = ((lane >> 4) & 1) * 8 + (lane & 7);
        const int bck = (lane >> 3) & 1;

#pragma unroll
        for (int p = 0; p < 3; p++) {
            uint32_t aBase = sb + ((p == 2) ? XP_OFF_AL : XP_OFF_AH);
            uint32_t bBase = sb + ((p == 1) ? XP_OFF_BL : XP_OFF_BH);
#pragma unroll
            for (int kk = 0; kk < 4; kk++) {
                uint32_t afrag[2][4], bfrag[8][2];
#pragma unroll
                for (int mt = 0; mt < 2; mt++)
                    ldsm_x4(lm_addr(aBase, wm * 32 + mt * 16 + arow, kk * 2 + ack),
                            afrag[mt]);
#pragma unroll
                for (int np = 0; np < 4; np++) {
                    uint32_t r4[4];
                    ldsm_x4(lm_addr(bBase, wn * 64 + np * 16 + brow, kk * 2 + bck), r4);
                    bfrag[np * 2][0] = r4[0]; bfrag[np * 2][1] = r4[1];
                    bfrag[np * 2 + 1][0] = r4[2]; bfrag[np * 2 + 1][1] = r4[3];
                }
#pragma unroll
                for (int mt = 0; mt < 2; mt++)
#pragma unroll
                    for (int nt = 0; nt < 8; nt++)
                        mma16816(acc[mt][nt], afrag[mt], bfrag[nt]);
            }
        }
    }

#pragma unroll
    for (int mt = 0; mt < 2; mt++) {
#pragma unroll
        for (int nt = 0; nt < 8; nt++) {
            int m = m0 + wm * 32 + mt * 16 + (lane >> 2);
            int nl = wn * 64 + nt * 8 + (lane & 3) * 2;
            float2 o0, o1;
            o0.x = acc[mt][nt][0] + sbias[nl];
            o0.y = acc[mt][nt][1] + sbias[nl + 1];
            o1.x = acc[mt][nt][2] + sbias[nl];
            o1.y = acc[mt][nt][3] + sbias[nl + 1];
            *(float2*)&out[(size_t)m * Hdim + n0 + nl] = o0;
            *(float2*)&out[(size_t)(m + 8) * Hdim + n0 + nl] = o1;
        }
    }
}

// ============================================================================
// Fused dual-layer recurrence. 128 CTAs x 256 threads, 196608B dynamic SMEM.
// Cohort A (0..63): rec0 (16 j, W frags IN REGISTERS) + inline xp2 (16 cols,
//   W in SMEM). 4 phases x 256-k chunks, double-buffered 64KB stages.
// Cohort B (64..127): rec1 (16 j, W frags IN REGISTERS), 4 phases,
//   triple-buffered 64KB stages, gated on g_stepA.
// ============================================================================
#define RNN_SMEM_BYTES 196608
// cohort A layout
#define A_WX_H   0
#define A_WX_L   32768
#define A_WR_H   65536     /* temp; region becomes stage buf 0 */
#define A_WR_L   98304
#define A_S0     65536
#define A_S1     131072
// cohort B layout
#define B_S0     0
#define B_S1     65536
#define B_S2     131072    /* also temp W staging during init */
#define B_WT_H   131072
#define B_WT_L   163840

// stage one 256-k chunk of h (hi+lo) into a 64KB buffer (rows=b, 512B, SW)
static __device__ __forceinline__ void stage_h256(
    const __nv_bfloat16* __restrict__ hh, const __nv_bfloat16* __restrict__ hl,
    int kc, char* dst, int tid)
{
#pragma unroll
    for (int r = 0; r < 8; r++) {
        int idx = r * 256 + tid;
        int b = idx >> 5;
        int lg = idx & 31;
        uint32_t d = smem_u32(dst + b * 512 + ((lg ^ (b & 7)) << 4));
        const __nv_bfloat16* s = hh + b * Hdim + kc * 256 + lg * 8;
        asm volatile("cp.async.cg.shared.global [%0], [%1], 16;" ::"r"(d), "l"(s));
        const __nv_bfloat16* s2 = hl + b * Hdim + kc * 256 + lg * 8;
        asm volatile("cp.async.cg.shared.global [%0], [%1], 16;"
                     ::"r"(d + 32768), "l"(s2));
    }
}

__global__ void __launch_bounds__(256) rnn_fused_kernel(
    const float* __restrict__ xp0, const float* __restrict__ Whh0,
    const float* __restrict__ Wih1, const float* __restrict__ bi1,
    const float* __restrict__ bh1, const float* __restrict__ Whh1,
    float* __restrict__ xp2)
{
    extern __shared__ __align__(1024) char smraw[];
    const int tid = threadIdx.x;
    const int bid = blockIdx.x;
    const int wid = tid >> 5;
    const int lane = tid & 31;

    if (bid == 0 && tid == 0)
        asm volatile("st.relaxed.gpu.global.u32 [%0], %1;"
                     :: "l"(&g_stepA), "r"(0u) : "memory");

    // ldmatrix lane mappings
    const int asub = lane >> 3;
    const int arow = (asub & 1) * 8 + (lane & 7);
    const int ack = asub >> 1;
    const int brow = ((lane >> 4) & 1) * 8 + (lane & 7);
    const int bck = (lane >> 3) & 1;
    const int eb = tid >> 2;
    const int ej = (tid & 3) * 4;

    if (bid < 64) {
        // ==================== Cohort A ====================
        const int j0 = bid * 16;
        float* p_s = (float*)(smraw + A_S0);   // partials alias stage buf 0

        // W staging: xp W (Wih1) permanent at [0,64K); rec W (Whh0) temp.
        for (int i = tid; i < 8192; i += 256) {
            int row = i >> 8;                  // 0..31: 0-15 rec, 16-31 xp
            int col4 = i & 255;
            bool isrec = row < 16;
            int r = row & 15;
            const float* src = isrec
                ? &Whh0[(size_t)(j0 + r) * Hdim + col4 * 4]
                : &Wih1[(size_t)(j0 + r) * Hdim + col4 * 4];
            uint2 hi, lo;
            split_bf16(*(const float4*)src, hi, lo);
            int g = col4 >> 1;
            int off = r * 2048 + ((g ^ (r & 7)) << 4) + (col4 & 1) * 8;
            int base = isrec ? A_WR_H : A_WX_H;
            *(uint2*)(smraw + base + off) = hi;
            *(uint2*)(smraw + base + 32768 + off) = lo;
        }
        // zero h1 slot 0 (owned 16 columns)
        if (tid < 64) {
            uint4 z = make_uint4(0, 0, 0, 0);
            *(uint4*)&g_hh1[0][(size_t)tid * Hdim + j0] = z;
            *(uint4*)&g_hh1[0][(size_t)tid * Hdim + j0 + 8] = z;
            *(uint4*)&g_hl1[0][(size_t)tid * Hdim + j0] = z;
            *(uint4*)&g_hl1[0][(size_t)tid * Hdim + j0 + 8] = z;
        }
        float bias2[4];
#pragma unroll
        for (int i = 0; i < 4; i++)
            bias2[i] = bi1[j0 + ej + i] + bh1[j0 + ej + i];
        __syncthreads();

        // preload rec-W fragments into registers (8 k16-tiles per warp)
        uint32_t wRh[8][4], wRl[8][4];
#pragma unroll
        for (int c = 0; c < 4; c++)
#pragma unroll
            for (int s2 = 0; s2 < 2; s2++) {
                int idx = c * 2 + s2;
                int gB = (c * 16 + wid * 2 + s2) * 2 + bck;
                uint32_t sw = (uint32_t)((gB ^ (brow & 7)) << 4);
                ldsm_x4(smem_u32(smraw + A_WR_H) + brow * 2048 + sw, wRh[idx]);
                ldsm_x4(smem_u32(smraw + A_WR_L) + brow * 2048 + sw, wRl[idx]);
            }
        grid_sync_p(&g_barG_cnt, &g_barG_gen, 128);

#pragma unroll 1
        for (int s = 0; s <= Sdim; s++) {
            const __nv_bfloat16* hh_in = g_hh1[s & 1];
            const __nv_bfloat16* hl_in = g_hl1[s & 1];
            __nv_bfloat16* hh_out = g_hh1[(s + 1) & 1];
            __nv_bfloat16* hl_out = g_hl1[(s + 1) & 1];

            int tt = (s < Sdim) ? s : Sdim - 1;
            float4 xpv = *(const float4*)&xp0[((size_t)eb * Sdim + tt) * Hdim
                                              + j0 + ej];

            float accR[4][2][4], accX[4][2][4];
#pragma unroll
            for (int mt = 0; mt < 4; mt++)
#pragma unroll
                for (int nt = 0; nt < 2; nt++)
#pragma unroll
                    for (int i = 0; i < 4; i++) {
                        accR[mt][nt][i] = 0.0f;
                        accX[mt][nt][i] = 0.0f;
                    }

            stage_h256(hh_in, hl_in, 0, smraw + A_S0, tid);
            asm volatile("cp.async.commit_group;");
            stage_h256(hh_in, hl_in, 1, smraw + A_S1, tid);
            asm volatile("cp.async.commit_group;");

#pragma unroll
            for (int c = 0; c < 4; c++) {
                if (c < 3) asm volatile("cp.async.wait_group 1;");
                else       asm volatile("cp.async.wait_group 0;");
                __syncthreads();

                const uint32_t shb = smem_u32(smraw + ((c & 1) ? A_S1 : A_S0));
                const uint32_t slb = shb + 32768;
                const uint32_t wxh = smem_u32(smraw + A_WX_H);
                const uint32_t wxl = smem_u32(smraw + A_WX_L);

#pragma unroll
                for (int s2 = 0; s2 < 2; s2++) {
                    const int idx = c * 2 + s2;
                    uint32_t ah[4][4], al[4][4];
                    int gA = wid * 4 + s2 * 2 + ack;
#pragma unroll
                    for (int mt = 0; mt < 4; mt++) {
                        int row = mt * 16 + arow;
                        uint32_t sw = (uint32_t)((gA ^ (row & 7)) << 4);
                        ldsm_x4(shb + row * 512 + sw, ah[mt]);
                        ldsm_x4(slb + row * 512 + sw, al[mt]);
                    }
                    int gB = (c * 16 + wid * 2 + s2) * 2 + bck;
                    uint32_t bsw = (uint32_t)((gB ^ (brow & 7)) << 4);
                    uint32_t xh[4], xl[4];
                    ldsm_x4(wxh + brow * 2048 + bsw, xh);
                    ldsm_x4(wxl + brow * 2048 + bsw, xl);

#pragma unroll
                    for (int mt = 0; mt < 4; mt++) {
                        mma16816(accR[mt][0], ah[mt], &wRh[idx][0]);
                        mma16816(accR[mt][1], ah[mt], &wRh[idx][2]);
                        mma16816(accR[mt][0], ah[mt], &wRl[idx][0]);
                        mma16816(accR[mt][1], ah[mt], &wRl[idx][2]);
                        mma16816(accR[mt][0], al[mt], &wRh[idx][0]);
                        mma16816(accR[mt][1], al[mt], &wRh[idx][2]);
                        mma16816(accX[mt][0], ah[mt], &xh[0]);
                        mma16816(accX[mt][1], ah[mt], &xh[2]);
                        mma16816(accX[mt][0], ah[mt], &xl[0]);
                        mma16816(accX[mt][1], ah[mt], &xl[2]);
                        mma16816(accX[mt][0], al[mt], &xh[0]);
                        mma16816(accX[mt][1], al[mt], &xh[2]);
                    }
                }
                if (c < 2) {
                    __syncthreads();     // all warps done reading this buffer
                    stage_h256(hh_in, hl_in, c + 2,
                               smraw + ((c & 1) ? A_S1 : A_S0), tid);
                    asm volatile("cp.async.commit_group;");
                }
            }
            // phase-3 top sync guaranteed all warps finished phase 2 (buf0);
            // partial writes to p_s (= buf0) are safe.
#pragma unroll
            for (int mt = 0; mt < 4; mt++)
#pragma unroll
                for (int nt = 0; nt < 2; nt++) {
                    int b = mt * 16 + (lane >> 2);
                    int j = nt * 8 + (lane & 3) * 2;
                    *(float2*)&p_s[wid * 1024 + b * 16 + j] =
                        make_float2(accR[mt][nt][0], accR[mt][nt][1]);
                    *(float2*)&p_s[wid * 1024 + (b + 8) * 16 + j] =
                        make_float2(accR[mt][nt][2], accR[mt][nt][3]);
                    *(float2*)&p_s[8192 + wid * 1024 + b * 16 + j] =
                        make_float2(accX[mt][nt][0], accX[mt][nt][1]);
                    *(float2*)&p_s[8192 + wid * 1024 + (b + 8) * 16 + j] =
                        make_float2(accX[mt][nt][2], accX[mt][nt][3]);
                }
            __syncthreads();

            {
                int o = tid * 4;
                float4 sr = *(const float4*)&p_s[o];
                float4 sx = *(const float4*)&p_s[8192 + o];
#pragma unroll
                for (int w = 1; w < 8; w++) {
                    float4 q = *(const float4*)&p_s[w * 1024 + o];
                    sr.x += q.x; sr.y += q.y; sr.z += q.z; sr.w += q.w;
                    float4 q2 = *(const float4*)&p_s[8192 + w * 1024 + o];
                    sx.x += q2.x; sx.y += q2.y; sx.z += q2.z; sx.w += q2.w;
                }
                if (s < Sdim) {
                    float v0 = tanhf(sr.x + xpv.x);
                    float v1 = tanhf(sr.y + xpv.y);
                    float v2 = tanhf(sr.z + xpv.z);
                    float v3 = tanhf(sr.w + xpv.w);
                    uint2 hi, lo;
                    split_bf16(make_float4(v0, v1, v2, v3), hi, lo);
                    size_t ho = (size_t)eb * Hdim + j0 + ej;
                    *(uint2*)&hh_out[ho] = hi;
                    *(uint2*)&hl_out[ho] = lo;
                }
                if (s >= 1) {
                    float4 o4;
                    o4.x = sx.x + bias2[0];
                    o4.y = sx.y + bias2[1];
                    o4.z = sx.z + bias2[2];
                    o4.w = sx.w + bias2[3];
                    *(float4*)&xp2[((size_t)(s - 1) * Bdim + eb) * Hdim + j0 + ej]
                        = o4;
                }
            }
            __syncthreads();
            if (s >= 1 && tid == 0)
                asm volatile("red.release.gpu.global.add.u32 [%0], 1;"
                             :: "l"(&g_stepA) : "memory");
            if (s < Sdim) grid_sync_p(&g_barA_cnt, &g_barA_gen, 64);
        }
    } else {
        // ==================== Cohort B ====================
        const int j0 = (bid - 64) * 16;
        float* p_s = (float*)(smraw + B_S0);

        // rec1 W -> temp SMEM (buf2 region)
        for (int i = tid; i < 4096; i += 256) {
            int j = i >> 8;
            int col4 = i & 255;
            uint2 hi, lo;
            split_bf16(*(const float4*)&Whh1[(size_t)(j0 + j) * Hdim + col4 * 4],
                       hi, lo);
            int g = col4 >> 1;
            int off = j * 2048 + ((g ^ (j & 7)) << 4) + (col4 & 1) * 8;
            *(uint2*)(smraw + B_WT_H + off) = hi;
            *(uint2*)(smraw + B_WT_L + off) = lo;
        }
        if (tid < 64) {
            uint4 z = make_uint4(0, 0, 0, 0);
            *(uint4*)&g_hh2[0][(size_t)tid * Hdim + j0] = z;
            *(uint4*)&g_hh2[0][(size_t)tid * Hdim + j0 + 8] = z;
            *(uint4*)&g_hl2[0][(size_t)tid * Hdim + j0] = z;
            *(uint4*)&g_hl2[0][(size_t)tid * Hdim + j0 + 8] = z;
        }
        __syncthreads();

        // preload all rec1 W fragments into registers
        uint32_t wBh[8][4], wBl[8][4];
#pragma unroll
        for (int c = 0; c < 4; c++)
#pragma unroll
            for (int s2 = 0; s2 < 2; s2++) {
                int idx = c * 2 + s2;
                int gB = (c * 16 + wid * 2 + s2) * 2 + bck;
                uint32_t sw = (uint32_t)((gB ^ (brow & 7)) << 4);
                ldsm_x4(smem_u32(smraw + B_WT_H) + brow * 2048 + sw, wBh[idx]);
                ldsm_x4(smem_u32(smraw + B_WT_L) + brow * 2048 + sw, wBl[idx]);
            }
        grid_sync_p(&g_barG_cnt, &g_barG_gen, 128);

#pragma unroll 1
        for (int t = 0; t < Sdim; t++) {
            // gate: xp2[t] published by cohort A (count = 64*(t+1))
            if (tid == 0) {
                unsigned tgt = 64u * (unsigned)(t + 1);
                unsigned cur;
                do {
                    asm volatile("ld.acquire.gpu.global.u32 %0, [%1];"
                                 : "=r"(cur) : "l"(&g_stepA) : "memory");
                } while (cur < tgt);
            }
            __syncthreads();

            const __nv_bfloat16* hh_in = g_hh2[t & 1];
            const __nv_bfloat16* hl_in = g_hl2[t & 1];
            __nv_bfloat16* hh_out = g_hh2[(t + 1) & 1];
            __nv_bfloat16* hl_out = g_hl2[(t + 1) & 1];

            float4 xpv = *(const float4*)&xp2[((size_t)t * Bdim + eb) * Hdim
                                              + j0 + ej];

            float acc[4][2][4];
#pragma unroll
            for (int mt = 0; mt < 4; mt++)
#pragma unroll
                for (int nt = 0; nt < 2; nt++)
#pragma unroll
                    for (int i = 0; i < 4; i++) acc[mt][nt][i] = 0.0f;

            stage_h256(hh_in, hl_in, 0, smraw + B_S0, tid);
            asm volatile("cp.async.commit_group;");
            stage_h256(hh_in, hl_in, 1, smraw + B_S1, tid);
            asm volatile("cp.async.commit_group;");

#pragma unroll
            for (int c = 0; c < 4; c++) {
                if (c < 3) asm volatile("cp.async.wait_group 1;");
                else       asm volatile("cp.async.wait_group 0;");
                __syncthreads();

                const int bufi = c % 3;
                const uint32_t shb = smem_u32(smraw + (size_t)bufi * 65536);
                const uint32_t slb = shb + 32768;

#pragma unroll
                for (int s2 = 0; s2 < 2; s2++) {
                    const int idx = c * 2 + s2;
                    uint32_t ah[4][4], al[4][4];
                    int gA = wid * 4 + s2 * 2 + ack;
#pragma unroll
                    for (int mt = 0; mt < 4; mt++) {
                        int row = mt * 16 + arow;
                        uint32_t sw = (uint32_t)((gA ^ (row & 7)) << 4);
                        ldsm_x4(shb + row * 512 + sw, ah[mt]);
                        ldsm_x4(slb + row * 512 + sw, al[mt]);
                    }
#pragma unroll
                    for (int mt = 0; mt < 4; mt++) {
                        mma16816(acc[mt][0], ah[mt], &wBh[idx][0]);
                        mma16816(acc[mt][1], ah[mt], &wBh[idx][2]);
                        mma16816(acc[mt][0], ah[mt], &wBl[idx][0]);
                        mma16816(acc[mt][1], ah[mt], &wBl[idx][2]);
                        mma16816(acc[mt][0], al[mt], &wBh[idx][0]);
                        mma16816(acc[mt][1], al[mt], &wBh[idx][2]);
                    }
                }
                if (c + 2 < 4) {
                    // target buf (c+2)%3 was last read in phase c-1; the
                    // top-of-phase sync already ordered those reads.
                    stage_h256(hh_in, hl_in, c + 2,
                               smraw + (size_t)((c + 2) % 3) * 65536, tid);
                    asm volatile("cp.async.commit_group;");
                }
            }
            __syncthreads();   // phase-3 reads of buf0 done before p_s writes

#pragma unroll
            for (int mt = 0; mt < 4; mt++)
#pragma unroll
                for (int nt = 0; nt < 2; nt++) {
                    int b = mt * 16 + (lane >> 2);
                    int j = nt * 8 + (lane & 3) * 2;
                    *(float2*)&p_s[wid * 1024 + b * 16 + j] =
                        make_float2(acc[mt][nt][0], acc[mt][nt][1]);
                    *(float2*)&p_s[wid * 1024 + (b + 8) * 16 + j] =
                        make_float2(acc[mt][nt][2], acc[mt][nt][3]);
                }
            __syncthreads();

            {
                int o = tid * 4;
                float4 s = *(const float4*)&p_s[o];
#pragma unroll
                for (int w = 1; w < 8; w++) {
                    float4 q = *(const float4*)&p_s[w * 1024 + o];
                    s.x += q.x; s.y += q.y; s.z += q.z; s.w += q.w;
                }
                float v0 = tanhf(s.x + xpv.x);
                float v1 = tanhf(s.y + xpv.y);
                float v2 = tanhf(s.z + xpv.z);
                float v3 = tanhf(s.w + xpv.w);
                uint2 hi, lo;
                split_bf16(make_float4(v0, v1, v2, v3), hi, lo);
                size_t ho = (size_t)eb * Hdim + j0 + ej;
                *(uint2*)&hh_out[ho] = hi;
                *(uint2*)&hl_out[ho] = lo;
            }
            grid_sync_p(&g_barB_cnt, &g_barB_gen, 64);
        }
    }
}

// ============================================================================
// Final FC + sigmoid: h_last = g_hh2[0] + g_hl2[0]  ((511+1)&1 = 0)
// ============================================================================
__global__ void fc_kernel(const __nv_bfloat16* __restrict__ hh,
                          const __nv_bfloat16* __restrict__ hl,
                          const float* __restrict__ fcw,
                          const float* __restrict__ fcb,
                          float* __restrict__ out)
{
    __shared__ float red[8];
    int b = blockIdx.x, tid = threadIdx.x;
    float s = 0.0f;
    for (int k = tid; k < Hdim; k += 256) {
        float h = __bfloat162float(hh[b * Hdim + k]) +
                  __bfloat162float(hl[b * Hdim + k]);
        s += h * fcw[k];
    }
#pragma unroll
    for (int o = 16; o; o >>= 1) s += __shfl_xor_sync(0xFFFFFFFFu, s, o);
    if ((tid & 31) == 0) red[tid >> 5] = s;
    __syncthreads();
    if (tid == 0) {
        float tot = 0.0f;
#pragma unroll
        for (int i = 0; i < 8; i++) tot += red[i];
        float logit = tot + fcb[0];
        out[b] = 1.0f / (1.0f + expf(-logit));
    }
}

// ============================================================================
extern "C" void kernel_launch(void* const* d_in, const int* in_sizes, int n_in,
                              void* d_out, int out_size)
{
    const float* x     = (const float*)d_in[0];
    const float* W_ih0 = (const float*)d_in[1];
    const float* W_hh0 = (const float*)d_in[2];
    const float* b_ih0 = (const float*)d_in[3];
    const float* b_hh0 = (const float*)d_in[4];
    const float* W_ih1 = (const float*)d_in[5];
    const float* W_hh1 = (const float*)d_in[6];
    const float* b_ih1 = (const float*)d_in[7];
    const float* b_hh1 = (const float*)d_in[8];
    const float* fc_w  = (const float*)d_in[9];
    const float* fc_b  = (const float*)d_in[10];
    float* out = (float*)d_out;

    float *xp, *xp2;
    __nv_bfloat16 *hh2, *hl2;
    cudaGetSymbolAddress((void**)&xp, g_xp);
    cudaGetSymbolAddress((void**)&xp2, g_xp2);
    cudaGetSymbolAddress((void**)&hh2, g_hh2);
    cudaGetSymbolAddress((void**)&hl2, g_hl2);

    cudaFuncSetAttribute(rnn_fused_kernel,
                         cudaFuncAttributeMaxDynamicSharedMemorySize,
                         RNN_SMEM_BYTES);
    cudaFuncSetAttribute(xproj_mma_kernel<Fdim>,
                         cudaFuncAttributeMaxDynamicSharedMemorySize, XP_SMEM);

    dim3 xgrid(8, 256);
    // layer-0 xp: rows m = b*S + t -> xp[(b*S+t)*H + j]
    xproj_mma_kernel<Fdim><<<xgrid, 256, XP_SMEM>>>(x, W_ih0, b_ih0, b_hh0, xp);
    // fused dual-layer recurrence (A: rec0 + xp2; B: rec1)
    rnn_fused_kernel<<<128, 256, RNN_SMEM_BYTES>>>(
        xp, W_hh0, W_ih1, b_ih1, b_hh1, W_hh1, xp2);
    // head: final h2 in slot 0
    fc_kernel<<<64, 256>>>(hh2, hl2, fc_w, fc_b, out);
}